// round 6
// baseline (speedup 1.0000x reference)
#include <cuda_runtime.h>
#include <cuda_bf16.h>
#include <math.h>
#include <stdint.h>

#define S_LEN 2048
#define HID   2560
#define NH    32
#define NKV   8
#define HD    128
#define NQD   (NH*HD)    // 4096
#define NKD   (NKV*HD)   // 1024
#define NQKV  (NQD+2*NKD) // 6144

// fp32 combined QKV GEMM output: [s][6144]  (q:0..4095, k:4096..5119, v:5120..6143)
__device__ float g_qkv[S_LEN * NQKV];

// bf16 hi/lo scratch
__device__ __nv_bfloat16 g_hs_h[S_LEN*HID], g_hs_l[S_LEN*HID];
__device__ __nv_bfloat16 g_w_h[NQKV*HID],  g_w_l[NQKV*HID];    // combined Wq|Wk|Wv
__device__ __nv_bfloat16 g_wo_h[HID*NQD],  g_wo_l[HID*NQD];
__device__ __nv_bfloat16 g_qh[S_LEN*NQD],  g_ql[S_LEN*NQD];
__device__ __nv_bfloat16 g_kh[S_LEN*NKD],  g_kl[S_LEN*NKD];
__device__ __nv_bfloat16 g_vh[S_LEN*NKD],  g_vl[S_LEN*NKD];
__device__ __nv_bfloat16 g_oh[S_LEN*NQD],  g_ol[S_LEN*NQD];

// ---------------------------------------------------------------------------
__device__ __forceinline__ uint32_t s2u(const void* p) {
    uint32_t a;
    asm("{ .reg .u64 t; cvta.to.shared.u64 t, %1; cvt.u32.u64 %0, t; }" : "=r"(a) : "l"(p));
    return a;
}
__device__ __forceinline__ void ldsm_x4(uint32_t* r, uint32_t addr) {
    asm volatile("ldmatrix.sync.aligned.m8n8.x4.shared.b16 {%0,%1,%2,%3}, [%4];"
                 : "=r"(r[0]), "=r"(r[1]), "=r"(r[2]), "=r"(r[3]) : "r"(addr));
}
__device__ __forceinline__ void ldsm_x4_t(uint32_t* r, uint32_t addr) {
    asm volatile("ldmatrix.sync.aligned.m8n8.x4.trans.shared.b16 {%0,%1,%2,%3}, [%4];"
                 : "=r"(r[0]), "=r"(r[1]), "=r"(r[2]), "=r"(r[3]) : "r"(addr));
}
__device__ __forceinline__ void mma16816(float* c, const uint32_t* a, const uint32_t* b) {
    asm volatile("mma.sync.aligned.m16n8k16.row.col.f32.bf16.bf16.f32 "
                 "{%0,%1,%2,%3}, {%4,%5,%6,%7}, {%8,%9}, {%0,%1,%2,%3};"
                 : "+f"(c[0]), "+f"(c[1]), "+f"(c[2]), "+f"(c[3])
                 : "r"(a[0]), "r"(a[1]), "r"(a[2]), "r"(a[3]), "r"(b[0]), "r"(b[1]));
}
__device__ __forceinline__ void cp16(uint32_t dst, const void* src) {
    asm volatile("cp.async.cg.shared.global [%0], [%1], 16;" :: "r"(dst), "l"(src));
}
__device__ __forceinline__ uint32_t pack_bf2(float x, float y) {
    __nv_bfloat162 t = __float22bfloat162_rn(make_float2(x, y));
    return *(uint32_t*)&t;
}
__device__ __forceinline__ float bf_lo(float x) {
    return x - __bfloat162float(__float2bfloat16(x));
}

// ---------------------------------------------------------------------------
__global__ __launch_bounds__(256) void split_kernel(const float* __restrict__ x,
                                                    __nv_bfloat16* __restrict__ h,
                                                    __nv_bfloat16* __restrict__ l,
                                                    int n) {
    int i = blockIdx.x * blockDim.x + threadIdx.x;
    if (i < n) {
        float v = x[i];
        __nv_bfloat16 hb = __float2bfloat16(v);
        h[i] = hb;
        l[i] = __float2bfloat16(v - __bfloat162float(hb));
    }
}

// merged Wq|Wk|Wv split into contiguous combined buffer
#define WQN (NQD*HID)
#define WKN (NKD*HID)
__global__ __launch_bounds__(256) void split_weights(const float* __restrict__ wq,
                                                     const float* __restrict__ wk,
                                                     const float* __restrict__ wv,
                                                     __nv_bfloat16* __restrict__ h,
                                                     __nv_bfloat16* __restrict__ l) {
    int i = blockIdx.x * blockDim.x + threadIdx.x;
    if (i >= WQN + 2 * WKN) return;
    float v;
    if (i < WQN)            v = wq[i];
    else if (i < WQN + WKN) v = wk[i - WQN];
    else                    v = wv[i - WQN - WKN];
    __nv_bfloat16 hb = __float2bfloat16(v);
    h[i] = hb;
    l[i] = __float2bfloat16(v - __bfloat162float(hb));
}

// strided split: src row stride, ncols contiguous per row
__global__ __launch_bounds__(256) void split_strided(const float* __restrict__ x,
                                                     int stride, int ncols,
                                                     __nv_bfloat16* __restrict__ h,
                                                     __nv_bfloat16* __restrict__ l,
                                                     int n) {
    int i = blockIdx.x * blockDim.x + threadIdx.x;
    if (i < n) {
        float v = x[(size_t)(i / ncols) * stride + (i % ncols)];
        __nv_bfloat16 hb = __float2bfloat16(v);
        h[i] = hb;
        l[i] = __float2bfloat16(v - __bfloat162float(hb));
    }
}

// ---------------------------------------------------------------------------
// HMMA bf16-split GEMM: C[M,N] = (Ah+Al)[M,K] @ (Bh+Bl)[N,K]^T  (fp32 acc)
// 128x128 CTA tile, BK=32, 8 warps, 4-stage cp.async pipeline, 1 sync/chunk.
// ---------------------------------------------------------------------------
#define ROWB 80
#define TILE_BYTES  (128*ROWB)        // 10240
#define STAGE_BYTES (4*TILE_BYTES)    // 40960
#define GSTG 4
#define GEMM_DSM    (GSTG*STAGE_BYTES)

__global__ __launch_bounds__(256, 1) void gemm_tc(
    const __nv_bfloat16* __restrict__ Ah, const __nv_bfloat16* __restrict__ Al,
    const __nv_bfloat16* __restrict__ Bh, const __nv_bfloat16* __restrict__ Bl,
    float* __restrict__ C, int N, int K)
{
    extern __shared__ __align__(128) char sm_raw[];
    const uint32_t sbase = s2u(sm_raw);

    const int tid  = threadIdx.x;
    const int wid  = tid >> 5;
    const int lane = tid & 31;
    const int m0 = blockIdx.y * 128, n0 = blockIdx.x * 128;
    const int m0w = (wid >> 2) * 64, n0w = (wid & 3) * 32;

    const __nv_bfloat16* srcs[4] = {Ah, Al, Bh, Bl};

    auto load_stage = [&](int c, int st) {
        const int k0 = c * 32;
#pragma unroll
        for (int tl = 0; tl < 4; tl++) {
            const __nv_bfloat16* src = srcs[tl];
            const int rbase = (tl < 2) ? m0 : n0;
#pragma unroll
            for (int j = 0; j < 2; j++) {
                int chunk = tid + j * 256;
                int row = chunk >> 2, cpos = chunk & 3;
                uint32_t dst = sbase + st * STAGE_BYTES + tl * TILE_BYTES
                             + row * ROWB + cpos * 16;
                cp16(dst, src + (size_t)(rbase + row) * K + k0 + cpos * 8);
            }
        }
        asm volatile("cp.async.commit_group;" ::: "memory");
    };

    float acc[4][4][4];
#pragma unroll
    for (int a = 0; a < 4; a++)
#pragma unroll
        for (int b = 0; b < 4; b++)
#pragma unroll
            for (int c = 0; c < 4; c++) acc[a][b][c] = 0.f;

    const int NC = K / 32;
    load_stage(0, 0);
    if (1 < NC) load_stage(1, 1);
    if (2 < NC) load_stage(2, 2);

    int st = 0;
    for (int c = 0; c < NC; c++) {
        const int rem = NC - 1 - c;
        if (rem >= 2)      asm volatile("cp.async.wait_group 2;" ::: "memory");
        else if (rem == 1) asm volatile("cp.async.wait_group 1;" ::: "memory");
        else               asm volatile("cp.async.wait_group 0;" ::: "memory");
        __syncthreads();
        if (c + 3 < NC) {
            int st3 = st + 3; if (st3 >= GSTG) st3 -= GSTG;
            load_stage(c + 3, st3);
        }

        const uint32_t aBaseH = sbase + st * STAGE_BYTES;
        const uint32_t aBaseL = aBaseH + TILE_BYTES;
        const uint32_t bBaseH = aBaseH + 2 * TILE_BYTES;
        const uint32_t bBaseL = aBaseH + 3 * TILE_BYTES;

        const uint32_t aOffBase = (uint32_t)((m0w + (lane & 15)) * ROWB + (((lane >> 4) & 1) * 8) * 2);
        const uint32_t bOffBase = (uint32_t)((n0w + ((lane >> 1) & 8) + (lane & 7)) * ROWB + (lane & 8) * 2);

#pragma unroll
        for (int kk = 0; kk < 32; kk += 16) {
            uint32_t ah[4][4], al[4][4], bh[2][4], bl[2][4];
            const uint32_t aOff = aOffBase + kk * 2;
            const uint32_t bOff = bOffBase + kk * 2;
#pragma unroll
            for (int mt = 0; mt < 4; mt++) {
                ldsm_x4(ah[mt], aBaseH + aOff + mt * 16 * ROWB);
                ldsm_x4(al[mt], aBaseL + aOff + mt * 16 * ROWB);
            }
#pragma unroll
            for (int nt2 = 0; nt2 < 2; nt2++) {
                ldsm_x4(bh[nt2], bBaseH + bOff + nt2 * 16 * ROWB);
                ldsm_x4(bl[nt2], bBaseL + bOff + nt2 * 16 * ROWB);
            }
#pragma unroll
            for (int mt = 0; mt < 4; mt++)
#pragma unroll
                for (int nt = 0; nt < 4; nt++) {
                    const uint32_t* bhp = &bh[nt >> 1][(nt & 1) * 2];
                    const uint32_t* blp = &bl[nt >> 1][(nt & 1) * 2];
                    mma16816(acc[mt][nt], ah[mt], bhp);
                    mma16816(acc[mt][nt], ah[mt], blp);
                    mma16816(acc[mt][nt], al[mt], bhp);
                }
        }
        if (++st == GSTG) st = 0;
    }

    const int row0 = m0 + m0w + (lane >> 2);
    const int col0 = n0 + n0w + (lane & 3) * 2;
#pragma unroll
    for (int mt = 0; mt < 4; mt++)
#pragma unroll
        for (int nt = 0; nt < 4; nt++) {
            float* p0 = C + (size_t)(row0 + mt * 16) * N + col0 + nt * 8;
            *(float2*)p0 = make_float2(acc[mt][nt][0], acc[mt][nt][1]);
            float* p1 = p0 + 8 * (size_t)N;
            *(float2*)p1 = make_float2(acc[mt][nt][2], acc[mt][nt][3]);
        }
}

// ---------------------------------------------------------------------------
// Warp-per-head RMSNorm + RoPE -> bf16 hi/lo. 256 threads = 8 heads/block.
// Thread t of a warp holds dims 4t..4t+3; RoPE partner via shfl_xor 16.
// ---------------------------------------------------------------------------
__global__ __launch_bounds__(256) void rmsnorm_rope_split(
    const float* __restrict__ in, int in_stride, const float* __restrict__ w,
    const float* __restrict__ cosp, const float* __restrict__ sinp,
    int nheads, __nv_bfloat16* __restrict__ oh, __nv_bfloat16* __restrict__ ol)
{
    const int warp = threadIdx.x >> 5;
    const int lane = threadIdx.x & 31;
    const int s = blockIdx.x;
    const int h = blockIdx.y * 8 + warp;

    const float* row = in + (size_t)s * in_stride + h * HD;
    float4 x = *(const float4*)(row + lane * 4);

    float v = x.x * x.x + x.y * x.y + x.z * x.z + x.w * x.w;
#pragma unroll
    for (int o = 16; o > 0; o >>= 1) v += __shfl_xor_sync(0xffffffffu, v, o);
    float r = rsqrtf(v * (1.0f / HD) + 1e-6f);

    float4 wv = *(const float4*)(w + lane * 4);
    float4 nx = make_float4(x.x * r * wv.x, x.y * r * wv.y, x.z * r * wv.z, x.w * r * wv.w);

    float4 p;
    p.x = __shfl_xor_sync(0xffffffffu, nx.x, 16);
    p.y = __shfl_xor_sync(0xffffffffu, nx.y, 16);
    p.z = __shfl_xor_sync(0xffffffffu, nx.z, 16);
    p.w = __shfl_xor_sync(0xffffffffu, nx.w, 16);
    const float sgn = (lane < 16) ? -1.f : 1.f;

    float4 c = *(const float4*)(cosp + s * HD + lane * 4);
    float4 sn = *(const float4*)(sinp + s * HD + lane * 4);
    float y0 = nx.x * c.x + sgn * p.x * sn.x;
    float y1 = nx.y * c.y + sgn * p.y * sn.y;
    float y2 = nx.z * c.z + sgn * p.z * sn.z;
    float y3 = nx.w * c.w + sgn * p.w * sn.w;

    const size_t idx = ((size_t)s * nheads + h) * HD + lane * 4;
    __nv_bfloat162 h0 = __float22bfloat162_rn(make_float2(y0, y1));
    __nv_bfloat162 h1 = __float22bfloat162_rn(make_float2(y2, y3));
    *(__nv_bfloat162*)(oh + idx)     = h0;
    *(__nv_bfloat162*)(oh + idx + 2) = h1;
    *(__nv_bfloat162*)(ol + idx)     = __float22bfloat162_rn(
        make_float2(y0 - __bfloat162float(__low2bfloat16(h0)),
                    y1 - __bfloat162float(__high2bfloat16(h0))));
    *(__nv_bfloat162*)(ol + idx + 2) = __float22bfloat162_rn(
        make_float2(y2 - __bfloat162float(__low2bfloat16(h1)),
                    y3 - __bfloat162float(__high2bfloat16(h1))));
}

// ---------------------------------------------------------------------------
// HMMA flash attention, bf16 hi/lo, 3-stage cp.async pipeline, 1 sync/tile.
// CTA: 128 queries x 1 head, 8 warps. KV tiles of 64. Heavy-first 1D grid.
// ---------------------------------------------------------------------------
#define AQ    128
#define AK    64
#define AROW  272
#define ATILE (64*AROW)           // 17408
#define ASTG  (4*ATILE)           // 69632
#define QTILE (128*AROW)          // 34816
#define NSTG  3
#define ADSM  (NSTG*ASTG)         // 208896

__global__ __launch_bounds__(256, 1) void attention_tc(
    const __nv_bfloat16* __restrict__ qh, const __nv_bfloat16* __restrict__ ql,
    const __nv_bfloat16* __restrict__ kh, const __nv_bfloat16* __restrict__ kl,
    const __nv_bfloat16* __restrict__ vh, const __nv_bfloat16* __restrict__ vl,
    __nv_bfloat16* __restrict__ oh, __nv_bfloat16* __restrict__ ol)
{
    extern __shared__ __align__(128) char sm_raw[];
    const uint32_t sbase = s2u(sm_raw);
    const int tid = threadIdx.x, wid = tid >> 5, lane = tid & 31;
    // heavy-first: highest m-chunks dispatched first, all heads interleaved
    const int h  = blockIdx.x & (NH - 1);
    const int m0 = (S_LEN / AQ - 1 - (blockIdx.x >> 5)) * AQ;
    const int hk = h >> 2;
    const float scale = 0.08838834764831845f;

    // ---- stage Q (hi/lo) into smem (stage-0 region), then registers
#pragma unroll
    for (int i = 0; i < 16; i++) {
        int c = tid + i * 256;
        int t = c >> 11;
        int row = (c >> 4) & 127, pos = c & 15;
        const __nv_bfloat16* src = t ? ql : qh;
        cp16(sbase + t * QTILE + row * AROW + pos * 16,
             src + ((size_t)(m0 + row) * NH + h) * HD + pos * 8);
    }
    asm volatile("cp.async.commit_group;" ::: "memory");
    asm volatile("cp.async.wait_group 0;" ::: "memory");
    __syncthreads();

    uint32_t qfh[8][4], qfl[8][4];
    {
        const uint32_t aOff = (uint32_t)((wid * 16 + (lane & 15)) * AROW + ((lane >> 4) & 1) * 16);
#pragma unroll
        for (int ks = 0; ks < 8; ks++) {
            ldsm_x4(qfh[ks], sbase + aOff + ks * 32);
            ldsm_x4(qfl[ks], sbase + QTILE + aOff + ks * 32);
        }
    }
    __syncthreads();

    auto load_kv = [&](int t, int st) {
        const int n0 = t * AK;
#pragma unroll
        for (int i = 0; i < 16; i++) {
            int c = tid + i * 256;
            int tl = c >> 10;
            int row = (c >> 4) & 63, pos = c & 15;
            const __nv_bfloat16* src = (tl == 0) ? kh : (tl == 1) ? kl : (tl == 2) ? vh : vl;
            cp16(sbase + st * ASTG + tl * ATILE + row * AROW + pos * 16,
                 src + ((size_t)(n0 + row) * NKV + hk) * HD + pos * 8);
        }
        asm volatile("cp.async.commit_group;" ::: "memory");
    };

    float out[16][4];
#pragma unroll
    for (int i = 0; i < 16; i++)
#pragma unroll
        for (int j = 0; j < 4; j++) out[i][j] = 0.f;
    float mlo = -INFINITY, mhi = -INFINITY, llo = 0.f, lhi = 0.f;

    const int row_lo = m0 + wid * 16 + (lane >> 2);
    const int row_hi = row_lo + 8;
    const int wlast  = m0 + wid * 16 + 15;

    const int NT = m0 / AK + 2;
    load_kv(0, 0);
    if (1 < NT) load_kv(1, 1);

    int st = 0;
    for (int t = 0; t < NT; t++) {
        const int n0 = t * AK;
        const int rem = NT - 1 - t;
        if (rem >= 1) asm volatile("cp.async.wait_group 1;" ::: "memory");
        else          asm volatile("cp.async.wait_group 0;" ::: "memory");
        __syncthreads();
        if (t + 2 < NT) {
            int st2 = st + 2; if (st2 >= NSTG) st2 -= NSTG;
            load_kv(t + 2, st2);
        }

        if (n0 <= wlast) {
            const uint32_t Kh = sbase + st * ASTG;
            const uint32_t Kl = Kh + ATILE;
            const uint32_t Vh = Kh + 2 * ATILE;
            const uint32_t Vl = Kh + 3 * ATILE;

            // ---- QK^T
            float sc[8][4];
#pragma unroll
            for (int i = 0; i < 8; i++)
#pragma unroll
                for (int j = 0; j < 4; j++) sc[i][j] = 0.f;

            const uint32_t bOff = (uint32_t)((((lane >> 1) & 8) + (lane & 7)) * AROW + (lane & 8) * 2);
#pragma unroll
            for (int ks = 0; ks < 8; ks++) {
#pragma unroll
                for (int nt2 = 0; nt2 < 4; nt2++) {
                    uint32_t kbh[4], kbl[4];
                    uint32_t o = bOff + nt2 * 16 * AROW + ks * 32;
                    ldsm_x4(kbh, Kh + o);
                    ldsm_x4(kbl, Kl + o);
#pragma unroll
                    for (int half = 0; half < 2; half++) {
                        float* c = sc[2 * nt2 + half];
                        mma16816(c, qfh[ks], &kbh[half * 2]);
                        mma16816(c, qfh[ks], &kbl[half * 2]);
                        mma16816(c, qfl[ks], &kbh[half * 2]);
                    }
                }
            }

            // ---- scale + causal mask + online softmax
            float tmax0 = -INFINITY, tmax1 = -INFINITY;
#pragma unroll
            for (int nt = 0; nt < 8; nt++) {
                int colb = n0 + nt * 8 + (lane & 3) * 2;
#pragma unroll
                for (int j = 0; j < 4; j++) {
                    float v = sc[nt][j] * scale;
                    int col = colb + (j & 1);
                    int row = (j < 2) ? row_lo : row_hi;
                    if (col > row) v = -INFINITY;
                    sc[nt][j] = v;
                    if (j < 2) tmax0 = fmaxf(tmax0, v); else tmax1 = fmaxf(tmax1, v);
                }
            }
            tmax0 = fmaxf(tmax0, __shfl_xor_sync(0xffffffffu, tmax0, 1));
            tmax0 = fmaxf(tmax0, __shfl_xor_sync(0xffffffffu, tmax0, 2));
            tmax1 = fmaxf(tmax1, __shfl_xor_sync(0xffffffffu, tmax1, 1));
            tmax1 = fmaxf(tmax1, __shfl_xor_sync(0xffffffffu, tmax1, 2));

            float mn0 = fmaxf(mlo, tmax0), mn1 = fmaxf(mhi, tmax1);
            float c0 = __expf(mlo - mn0),  c1 = __expf(mhi - mn1);
            float s0 = 0.f, s1 = 0.f;
#pragma unroll
            for (int nt = 0; nt < 8; nt++) {
                float p0 = __expf(sc[nt][0] - mn0);
                float p1 = __expf(sc[nt][1] - mn0);
                float p2 = __expf(sc[nt][2] - mn1);
                float p3 = __expf(sc[nt][3] - mn1);
                sc[nt][0] = p0; sc[nt][1] = p1; sc[nt][2] = p2; sc[nt][3] = p3;
                s0 += p0 + p1; s1 += p2 + p3;
            }
            s0 += __shfl_xor_sync(0xffffffffu, s0, 1);
            s0 += __shfl_xor_sync(0xffffffffu, s0, 2);
            s1 += __shfl_xor_sync(0xffffffffu, s1, 1);
            s1 += __shfl_xor_sync(0xffffffffu, s1, 2);
            llo = llo * c0 + s0;  lhi = lhi * c1 + s1;
            mlo = mn0;  mhi = mn1;
#pragma unroll
            for (int nt = 0; nt < 16; nt++) {
                out[nt][0] *= c0; out[nt][1] *= c0;
                out[nt][2] *= c1; out[nt][3] *= c1;
            }

            // ---- P @ V
#pragma unroll
            for (int b = 0; b < 4; b++) {
                uint32_t ph[4], pl[4];
                ph[0] = pack_bf2(sc[2*b][0],   sc[2*b][1]);
                ph[1] = pack_bf2(sc[2*b][2],   sc[2*b][3]);
                ph[2] = pack_bf2(sc[2*b+1][0], sc[2*b+1][1]);
                ph[3] = pack_bf2(sc[2*b+1][2], sc[2*b+1][3]);
                pl[0] = pack_bf2(bf_lo(sc[2*b][0]),   bf_lo(sc[2*b][1]));
                pl[1] = pack_bf2(bf_lo(sc[2*b][2]),   bf_lo(sc[2*b][3]));
                pl[2] = pack_bf2(bf_lo(sc[2*b+1][0]), bf_lo(sc[2*b+1][1]));
                pl[3] = pack_bf2(bf_lo(sc[2*b+1][2]), bf_lo(sc[2*b+1][3]));

                const uint32_t vrow = (uint32_t)((b * 16 + (lane & 15)) * AROW + (lane >> 4) * 16);
#pragma unroll
                for (int nbp = 0; nbp < 8; nbp++) {
                    uint32_t vbh[4], vbl[4];
                    uint32_t o = vrow + nbp * 32;
                    ldsm_x4_t(vbh, Vh + o);
                    ldsm_x4_t(vbl, Vl + o);
#pragma unroll
                    for (int half = 0; half < 2; half++) {
                        float* c = out[2 * nbp + half];
                        mma16816(c, ph, &vbh[half * 2]);
                        mma16816(c, ph, &vbl[half * 2]);
                        mma16816(c, pl, &vbh[half * 2]);
                    }
                }
            }
        }
        if (++st == NSTG) st = 0;
    }

    // ---- epilogue: normalize, write bf16 hi/lo
    const float i0 = 1.f / llo, i1 = 1.f / lhi;
#pragma unroll
    for (int nt = 0; nt < 16; nt++) {
        int col = nt * 8 + (lane & 3) * 2;
        {
            float a = out[nt][0] * i0, b = out[nt][1] * i0;
            size_t idx = ((size_t)row_lo * NH + h) * HD + col;
            __nv_bfloat162 hv = __float22bfloat162_rn(make_float2(a, b));
            *(__nv_bfloat162*)(oh + idx) = hv;
            *(__nv_bfloat162*)(ol + idx) = __float22bfloat162_rn(
                make_float2(a - __bfloat162float(__low2bfloat16(hv)),
                            b - __bfloat162float(__high2bfloat16(hv))));
        }
        {
            float a = out[nt][2] * i1, b = out[nt][3] * i1;
            size_t idx = ((size_t)row_hi * NH + h) * HD + col;
            __nv_bfloat162 hv = __float22bfloat162_rn(make_float2(a, b));
            *(__nv_bfloat162*)(oh + idx) = hv;
            *(__nv_bfloat162*)(ol + idx) = __float22bfloat162_rn(
                make_float2(a - __bfloat162float(__low2bfloat16(hv)),
                            b - __bfloat162float(__high2bfloat16(hv))));
        }
    }
}

// ---------------------------------------------------------------------------
extern "C" void kernel_launch(void* const* d_in, const int* in_sizes, int n_in,
                              void* d_out, int out_size) {
    const float* hs   = (const float*)d_in[0];
    const float* cosp = (const float*)d_in[1];
    const float* sinp = (const float*)d_in[2];
    const float* Wq   = (const float*)d_in[3];
    const float* Wk   = (const float*)d_in[4];
    const float* Wv   = (const float*)d_in[5];
    const float* Wo   = (const float*)d_in[6];
    const float* qw   = (const float*)d_in[7];
    const float* kw   = (const float*)d_in[8];
    float* out = (float*)d_out;

    float* pqkv;
    cudaGetSymbolAddress((void**)&pqkv, g_qkv);

    __nv_bfloat16 *hsh,*hsl,*wh,*wl,*woh,*wol;
    __nv_bfloat16 *qh,*ql,*kh,*kl,*vh,*vl,*ohp,*olp;
    cudaGetSymbolAddress((void**)&hsh, g_hs_h); cudaGetSymbolAddress((void**)&hsl, g_hs_l);
    cudaGetSymbolAddress((void**)&wh,  g_w_h);  cudaGetSymbolAddress((void**)&wl,  g_w_l);
    cudaGetSymbolAddress((void**)&woh, g_wo_h); cudaGetSymbolAddress((void**)&wol, g_wo_l);
    cudaGetSymbolAddress((void**)&qh, g_qh); cudaGetSymbolAddress((void**)&ql, g_ql);
    cudaGetSymbolAddress((void**)&kh, g_kh); cudaGetSymbolAddress((void**)&kl, g_kl);
    cudaGetSymbolAddress((void**)&vh, g_vh); cudaGetSymbolAddress((void**)&vl, g_vl);
    cudaGetSymbolAddress((void**)&ohp, g_oh); cudaGetSymbolAddress((void**)&olp, g_ol);

    cudaFuncSetAttribute(gemm_tc, cudaFuncAttributeMaxDynamicSharedMemorySize, GEMM_DSM);
    cudaFuncSetAttribute(attention_tc, cudaFuncAttributeMaxDynamicSharedMemorySize, ADSM);

    // launch 1: hs split
    split_kernel<<<(S_LEN*HID + 255)/256, 256>>>(hs, hsh, hsl, S_LEN*HID);
    // launch 2: merged Wq|Wk|Wv split
    split_weights<<<(WQN + 2*WKN + 255)/256, 256>>>(Wq, Wk, Wv, wh, wl);
    // launch 3 (profiled slot): fused QKV projection [2048, 6144]
    gemm_tc<<<dim3(NQKV/128, S_LEN/128), 256, GEMM_DSM>>>(hsh, hsl, wh, wl, pqkv, NQKV, HID);

    // rmsnorm+rope -> bf16 hi/lo (warp per head)
    rmsnorm_rope_split<<<dim3(S_LEN, NH/8),  256>>>(pqkv,       NQKV, qw, cosp, sinp, NH,  qh, ql);
    rmsnorm_rope_split<<<dim3(S_LEN, NKV/8), 256>>>(pqkv + NQD, NQKV, kw, cosp, sinp, NKV, kh, kl);
    split_strided<<<(S_LEN*NKD + 255)/256, 256>>>(pqkv + NQD + NKD, NQKV, NKD, vh, vl, S_LEN*NKD);
    // Wo split (independent; before O-proj)
    split_kernel<<<(HID*NQD + 255)/256, 256>>>(Wo, woh, wol, HID*NQD);

    // flash attention (HMMA), heavy-first 1D grid
    attention_tc<<<(S_LEN/AQ) * NH, 256, ADSM>>>(qh, ql, kh, kl, vh, vl, ohp, olp);

    // output projection
    gemm_tc<<<dim3(HID/128, S_LEN/128), 256, GEMM_DSM>>>(ohp, olp, woh, wol, out, HID, NQD);
}

// round 8
// speedup vs baseline: 1.4589x; 1.4589x over previous
#include <cuda_runtime.h>
#include <cuda_bf16.h>
#include <math.h>
#include <stdint.h>

#define S_LEN 2048
#define HID   2560
#define NH    32
#define NKV   8
#define HD    128
#define NQD   (NH*HD)    // 4096
#define NKD   (NKV*HD)   // 1024
#define NQKV  (NQD+2*NKD) // 6144

// fp32 combined QKV GEMM output: [s][6144]  (q:0..4095, k:4096..5119, v:5120..6143)
__device__ float g_qkv[S_LEN * NQKV];

// bf16 hi/lo scratch
__device__ __nv_bfloat16 g_hs_h[S_LEN*HID], g_hs_l[S_LEN*HID];
__device__ __nv_bfloat16 g_w_h[NQKV*HID],  g_w_l[NQKV*HID];    // combined Wq|Wk|Wv
__device__ __nv_bfloat16 g_wo_h[HID*NQD],  g_wo_l[HID*NQD];
__device__ __nv_bfloat16 g_qh[S_LEN*NQD],  g_ql[S_LEN*NQD];
__device__ __nv_bfloat16 g_kh[S_LEN*NKD],  g_kl[S_LEN*NKD];
__device__ __nv_bfloat16 g_vh[S_LEN*NKD],  g_vl[S_LEN*NKD];
__device__ __nv_bfloat16 g_oh[S_LEN*NQD],  g_ol[S_LEN*NQD];

// ---------------------------------------------------------------------------
__device__ __forceinline__ uint32_t s2u(const void* p) {
    uint32_t a;
    asm("{ .reg .u64 t; cvta.to.shared.u64 t, %1; cvt.u32.u64 %0, t; }" : "=r"(a) : "l"(p));
    return a;
}
__device__ __forceinline__ void ldsm_x4(uint32_t* r, uint32_t addr) {
    asm volatile("ldmatrix.sync.aligned.m8n8.x4.shared.b16 {%0,%1,%2,%3}, [%4];"
                 : "=r"(r[0]), "=r"(r[1]), "=r"(r[2]), "=r"(r[3]) : "r"(addr));
}
__device__ __forceinline__ void ldsm_x4_t(uint32_t* r, uint32_t addr) {
    asm volatile("ldmatrix.sync.aligned.m8n8.x4.trans.shared.b16 {%0,%1,%2,%3}, [%4];"
                 : "=r"(r[0]), "=r"(r[1]), "=r"(r[2]), "=r"(r[3]) : "r"(addr));
}
__device__ __forceinline__ void mma16816(float* c, const uint32_t* a, const uint32_t* b) {
    asm volatile("mma.sync.aligned.m16n8k16.row.col.f32.bf16.bf16.f32 "
                 "{%0,%1,%2,%3}, {%4,%5,%6,%7}, {%8,%9}, {%0,%1,%2,%3};"
                 : "+f"(c[0]), "+f"(c[1]), "+f"(c[2]), "+f"(c[3])
                 : "r"(a[0]), "r"(a[1]), "r"(a[2]), "r"(a[3]), "r"(b[0]), "r"(b[1]));
}
__device__ __forceinline__ void cp16(uint32_t dst, const void* src) {
    asm volatile("cp.async.cg.shared.global [%0], [%1], 16;" :: "r"(dst), "l"(src));
}
__device__ __forceinline__ uint32_t pack_bf2(float x, float y) {
    __nv_bfloat162 t = __float22bfloat162_rn(make_float2(x, y));
    return *(uint32_t*)&t;
}
__device__ __forceinline__ float bf_lo(float x) {
    return x - __bfloat162float(__float2bfloat16(x));
}

// ---------------------------------------------------------------------------
__global__ __launch_bounds__(256) void split_kernel(const float* __restrict__ x,
                                                    __nv_bfloat16* __restrict__ h,
                                                    __nv_bfloat16* __restrict__ l,
                                                    int n) {
    int i = blockIdx.x * blockDim.x + threadIdx.x;
    if (i < n) {
        float v = x[i];
        __nv_bfloat16 hb = __float2bfloat16(v);
        h[i] = hb;
        l[i] = __float2bfloat16(v - __bfloat162float(hb));
    }
}

// merged Wq|Wk|Wv split into contiguous combined buffer
#define WQN (NQD*HID)
#define WKN (NKD*HID)
__global__ __launch_bounds__(256) void split_weights(const float* __restrict__ wq,
                                                     const float* __restrict__ wk,
                                                     const float* __restrict__ wv,
                                                     __nv_bfloat16* __restrict__ h,
                                                     __nv_bfloat16* __restrict__ l) {
    int i = blockIdx.x * blockDim.x + threadIdx.x;
    if (i >= WQN + 2 * WKN) return;
    float v;
    if (i < WQN)            v = wq[i];
    else if (i < WQN + WKN) v = wk[i - WQN];
    else                    v = wv[i - WQN - WKN];
    __nv_bfloat16 hb = __float2bfloat16(v);
    h[i] = hb;
    l[i] = __float2bfloat16(v - __bfloat162float(hb));
}

// strided split: src row stride, ncols contiguous per row
__global__ __launch_bounds__(256) void split_strided(const float* __restrict__ x,
                                                     int stride, int ncols,
                                                     __nv_bfloat16* __restrict__ h,
                                                     __nv_bfloat16* __restrict__ l,
                                                     int n) {
    int i = blockIdx.x * blockDim.x + threadIdx.x;
    if (i < n) {
        float v = x[(size_t)(i / ncols) * stride + (i % ncols)];
        __nv_bfloat16 hb = __float2bfloat16(v);
        h[i] = hb;
        l[i] = __float2bfloat16(v - __bfloat162float(hb));
    }
}

// ---------------------------------------------------------------------------
// HMMA bf16-split GEMM: C[M,N] = (Ah+Al)[M,K] @ (Bh+Bl)[N,K]^T  (fp32 acc)
// 128x128 CTA tile, BK=32, 8 warps, 4-stage cp.async pipeline, 1 sync/chunk.
// ---------------------------------------------------------------------------
#define ROWB 80
#define TILE_BYTES  (128*ROWB)        // 10240
#define STAGE_BYTES (4*TILE_BYTES)    // 40960
#define GSTG 4
#define GEMM_DSM    (GSTG*STAGE_BYTES)

__global__ __launch_bounds__(256, 1) void gemm_tc(
    const __nv_bfloat16* __restrict__ Ah, const __nv_bfloat16* __restrict__ Al,
    const __nv_bfloat16* __restrict__ Bh, const __nv_bfloat16* __restrict__ Bl,
    float* __restrict__ C, int N, int K)
{
    extern __shared__ __align__(128) char sm_raw[];
    const uint32_t sbase = s2u(sm_raw);

    const int tid  = threadIdx.x;
    const int wid  = tid >> 5;
    const int lane = tid & 31;
    const int m0 = blockIdx.y * 128, n0 = blockIdx.x * 128;
    const int m0w = (wid >> 2) * 64, n0w = (wid & 3) * 32;

    const __nv_bfloat16* srcs[4] = {Ah, Al, Bh, Bl};

    auto load_stage = [&](int c, int st) {
        const int k0 = c * 32;
#pragma unroll
        for (int tl = 0; tl < 4; tl++) {
            const __nv_bfloat16* src = srcs[tl];
            const int rbase = (tl < 2) ? m0 : n0;
#pragma unroll
            for (int j = 0; j < 2; j++) {
                int chunk = tid + j * 256;
                int row = chunk >> 2, cpos = chunk & 3;
                uint32_t dst = sbase + st * STAGE_BYTES + tl * TILE_BYTES
                             + row * ROWB + cpos * 16;
                cp16(dst, src + (size_t)(rbase + row) * K + k0 + cpos * 8);
            }
        }
        asm volatile("cp.async.commit_group;" ::: "memory");
    };

    float acc[4][4][4];
#pragma unroll
    for (int a = 0; a < 4; a++)
#pragma unroll
        for (int b = 0; b < 4; b++)
#pragma unroll
            for (int c = 0; c < 4; c++) acc[a][b][c] = 0.f;

    const int NC = K / 32;
    load_stage(0, 0);
    if (1 < NC) load_stage(1, 1);
    if (2 < NC) load_stage(2, 2);

    int st = 0;
    for (int c = 0; c < NC; c++) {
        const int rem = NC - 1 - c;
        if (rem >= 2)      asm volatile("cp.async.wait_group 2;" ::: "memory");
        else if (rem == 1) asm volatile("cp.async.wait_group 1;" ::: "memory");
        else               asm volatile("cp.async.wait_group 0;" ::: "memory");
        __syncthreads();
        if (c + 3 < NC) {
            int st3 = st + 3; if (st3 >= GSTG) st3 -= GSTG;
            load_stage(c + 3, st3);
        }

        const uint32_t aBaseH = sbase + st * STAGE_BYTES;
        const uint32_t aBaseL = aBaseH + TILE_BYTES;
        const uint32_t bBaseH = aBaseH + 2 * TILE_BYTES;
        const uint32_t bBaseL = aBaseH + 3 * TILE_BYTES;

        const uint32_t aOffBase = (uint32_t)((m0w + (lane & 15)) * ROWB + (((lane >> 4) & 1) * 8) * 2);
        const uint32_t bOffBase = (uint32_t)((n0w + ((lane >> 1) & 8) + (lane & 7)) * ROWB + (lane & 8) * 2);

#pragma unroll
        for (int kk = 0; kk < 32; kk += 16) {
            uint32_t ah[4][4], al[4][4], bh[2][4], bl[2][4];
            const uint32_t aOff = aOffBase + kk * 2;
            const uint32_t bOff = bOffBase + kk * 2;
#pragma unroll
            for (int mt = 0; mt < 4; mt++) {
                ldsm_x4(ah[mt], aBaseH + aOff + mt * 16 * ROWB);
                ldsm_x4(al[mt], aBaseL + aOff + mt * 16 * ROWB);
            }
#pragma unroll
            for (int nt2 = 0; nt2 < 2; nt2++) {
                ldsm_x4(bh[nt2], bBaseH + bOff + nt2 * 16 * ROWB);
                ldsm_x4(bl[nt2], bBaseL + bOff + nt2 * 16 * ROWB);
            }
#pragma unroll
            for (int mt = 0; mt < 4; mt++)
#pragma unroll
                for (int nt = 0; nt < 4; nt++) {
                    const uint32_t* bhp = &bh[nt >> 1][(nt & 1) * 2];
                    const uint32_t* blp = &bl[nt >> 1][(nt & 1) * 2];
                    mma16816(acc[mt][nt], ah[mt], bhp);
                    mma16816(acc[mt][nt], ah[mt], blp);
                    mma16816(acc[mt][nt], al[mt], bhp);
                }
        }
        if (++st == GSTG) st = 0;
    }

    const int row0 = m0 + m0w + (lane >> 2);
    const int col0 = n0 + n0w + (lane & 3) * 2;
#pragma unroll
    for (int mt = 0; mt < 4; mt++)
#pragma unroll
        for (int nt = 0; nt < 4; nt++) {
            float* p0 = C + (size_t)(row0 + mt * 16) * N + col0 + nt * 8;
            *(float2*)p0 = make_float2(acc[mt][nt][0], acc[mt][nt][1]);
            float* p1 = p0 + 8 * (size_t)N;
            *(float2*)p1 = make_float2(acc[mt][nt][2], acc[mt][nt][3]);
        }
}

// ---------------------------------------------------------------------------
// Warp-per-head RMSNorm + RoPE -> bf16 hi/lo. 256 threads = 8 heads/block.
// ---------------------------------------------------------------------------
__global__ __launch_bounds__(256) void rmsnorm_rope_split(
    const float* __restrict__ in, int in_stride, const float* __restrict__ w,
    const float* __restrict__ cosp, const float* __restrict__ sinp,
    int nheads, __nv_bfloat16* __restrict__ oh, __nv_bfloat16* __restrict__ ol)
{
    const int warp = threadIdx.x >> 5;
    const int lane = threadIdx.x & 31;
    const int s = blockIdx.x;
    const int h = blockIdx.y * 8 + warp;

    const float* row = in + (size_t)s * in_stride + h * HD;
    float4 x = *(const float4*)(row + lane * 4);

    float v = x.x * x.x + x.y * x.y + x.z * x.z + x.w * x.w;
#pragma unroll
    for (int o = 16; o > 0; o >>= 1) v += __shfl_xor_sync(0xffffffffu, v, o);
    float r = rsqrtf(v * (1.0f / HD) + 1e-6f);

    float4 wv = *(const float4*)(w + lane * 4);
    float4 nx = make_float4(x.x * r * wv.x, x.y * r * wv.y, x.z * r * wv.z, x.w * r * wv.w);

    float4 p;
    p.x = __shfl_xor_sync(0xffffffffu, nx.x, 16);
    p.y = __shfl_xor_sync(0xffffffffu, nx.y, 16);
    p.z = __shfl_xor_sync(0xffffffffu, nx.z, 16);
    p.w = __shfl_xor_sync(0xffffffffu, nx.w, 16);
    const float sgn = (lane < 16) ? -1.f : 1.f;

    float4 c = *(const float4*)(cosp + s * HD + lane * 4);
    float4 sn = *(const float4*)(sinp + s * HD + lane * 4);
    float y0 = nx.x * c.x + sgn * p.x * sn.x;
    float y1 = nx.y * c.y + sgn * p.y * sn.y;
    float y2 = nx.z * c.z + sgn * p.z * sn.z;
    float y3 = nx.w * c.w + sgn * p.w * sn.w;

    const size_t idx = ((size_t)s * nheads + h) * HD + lane * 4;
    __nv_bfloat162 h0 = __float22bfloat162_rn(make_float2(y0, y1));
    __nv_bfloat162 h1 = __float22bfloat162_rn(make_float2(y2, y3));
    *(__nv_bfloat162*)(oh + idx)     = h0;
    *(__nv_bfloat162*)(oh + idx + 2) = h1;
    *(__nv_bfloat162*)(ol + idx)     = __float22bfloat162_rn(
        make_float2(y0 - __bfloat162float(__low2bfloat16(h0)),
                    y1 - __bfloat162float(__high2bfloat16(h0))));
    *(__nv_bfloat162*)(ol + idx + 2) = __float22bfloat162_rn(
        make_float2(y2 - __bfloat162float(__low2bfloat16(h1)),
                    y3 - __bfloat162float(__high2bfloat16(h1))));
}

// ---------------------------------------------------------------------------
// HMMA flash attention, bf16 hi/lo, 3-stage cp.async pipeline, 1 sync/tile.
// CTA: 128 queries x 1 head, 8 warps. KV tiles of 64. 2-D grid (R5 layout).
// ---------------------------------------------------------------------------
#define AQ    128
#define AK    64
#define AROW  272
#define ATILE (64*AROW)           // 17408
#define ASTG  (4*ATILE)           // 69632
#define QTILE (128*AROW)          // 34816
#define NSTG  3
#define ADSM  (NSTG*ASTG)         // 208896

__global__ __launch_bounds__(256, 1) void attention_tc(
    const __nv_bfloat16* __restrict__ qh, const __nv_bfloat16* __restrict__ ql,
    const __nv_bfloat16* __restrict__ kh, const __nv_bfloat16* __restrict__ kl,
    const __nv_bfloat16* __restrict__ vh, const __nv_bfloat16* __restrict__ vl,
    __nv_bfloat16* __restrict__ oh, __nv_bfloat16* __restrict__ ol)
{
    extern __shared__ __align__(128) char sm_raw[];
    const uint32_t sbase = s2u(sm_raw);
    const int tid = threadIdx.x, wid = tid >> 5, lane = tid & 31;
    const int m0 = blockIdx.x * AQ;
    const int h = blockIdx.y, hk = h >> 2;
    const float scale = 0.08838834764831845f;

    // ---- stage Q (hi/lo) into smem (stage-0 region), then registers
#pragma unroll
    for (int i = 0; i < 16; i++) {
        int c = tid + i * 256;
        int t = c >> 11;
        int row = (c >> 4) & 127, pos = c & 15;
        const __nv_bfloat16* src = t ? ql : qh;
        cp16(sbase + t * QTILE + row * AROW + pos * 16,
             src + ((size_t)(m0 + row) * NH + h) * HD + pos * 8);
    }
    asm volatile("cp.async.commit_group;" ::: "memory");
    asm volatile("cp.async.wait_group 0;" ::: "memory");
    __syncthreads();

    uint32_t qfh[8][4], qfl[8][4];
    {
        const uint32_t aOff = (uint32_t)((wid * 16 + (lane & 15)) * AROW + ((lane >> 4) & 1) * 16);
#pragma unroll
        for (int ks = 0; ks < 8; ks++) {
            ldsm_x4(qfh[ks], sbase + aOff + ks * 32);
            ldsm_x4(qfl[ks], sbase + QTILE + aOff + ks * 32);
        }
    }
    __syncthreads();

    auto load_kv = [&](int t, int st) {
        const int n0 = t * AK;
#pragma unroll
        for (int i = 0; i < 16; i++) {
            int c = tid + i * 256;
            int tl = c >> 10;
            int row = (c >> 4) & 63, pos = c & 15;
            const __nv_bfloat16* src = (tl == 0) ? kh : (tl == 1) ? kl : (tl == 2) ? vh : vl;
            cp16(sbase + st * ASTG + tl * ATILE + row * AROW + pos * 16,
                 src + ((size_t)(n0 + row) * NKV + hk) * HD + pos * 8);
        }
        asm volatile("cp.async.commit_group;" ::: "memory");
    };

    float out[16][4];
#pragma unroll
    for (int i = 0; i < 16; i++)
#pragma unroll
        for (int j = 0; j < 4; j++) out[i][j] = 0.f;
    float mlo = -INFINITY, mhi = -INFINITY, llo = 0.f, lhi = 0.f;

    const int row_lo = m0 + wid * 16 + (lane >> 2);
    const int row_hi = row_lo + 8;
    const int wlast  = m0 + wid * 16 + 15;

    const int NT = m0 / AK + 2;
    load_kv(0, 0);
    if (1 < NT) load_kv(1, 1);

    int st = 0;
    for (int t = 0; t < NT; t++) {
        const int n0 = t * AK;
        const int rem = NT - 1 - t;
        if (rem >= 1) asm volatile("cp.async.wait_group 1;" ::: "memory");
        else          asm volatile("cp.async.wait_group 0;" ::: "memory");
        __syncthreads();
        if (t + 2 < NT) {
            int st2 = st + 2; if (st2 >= NSTG) st2 -= NSTG;
            load_kv(t + 2, st2);
        }

        if (n0 <= wlast) {
            const uint32_t Kh = sbase + st * ASTG;
            const uint32_t Kl = Kh + ATILE;
            const uint32_t Vh = Kh + 2 * ATILE;
            const uint32_t Vl = Kh + 3 * ATILE;

            // ---- QK^T
            float sc[8][4];
#pragma unroll
            for (int i = 0; i < 8; i++)
#pragma unroll
                for (int j = 0; j < 4; j++) sc[i][j] = 0.f;

            const uint32_t bOff = (uint32_t)((((lane >> 1) & 8) + (lane & 7)) * AROW + (lane & 8) * 2);
#pragma unroll
            for (int ks = 0; ks < 8; ks++) {
#pragma unroll
                for (int nt2 = 0; nt2 < 4; nt2++) {
                    uint32_t kbh[4], kbl[4];
                    uint32_t o = bOff + nt2 * 16 * AROW + ks * 32;
                    ldsm_x4(kbh, Kh + o);
                    ldsm_x4(kbl, Kl + o);
#pragma unroll
                    for (int half = 0; half < 2; half++) {
                        float* c = sc[2 * nt2 + half];
                        mma16816(c, qfh[ks], &kbh[half * 2]);
                        mma16816(c, qfh[ks], &kbl[half * 2]);
                        mma16816(c, qfl[ks], &kbh[half * 2]);
                    }
                }
            }

            // ---- scale + causal mask + online softmax
            float tmax0 = -INFINITY, tmax1 = -INFINITY;
#pragma unroll
            for (int nt = 0; nt < 8; nt++) {
                int colb = n0 + nt * 8 + (lane & 3) * 2;
#pragma unroll
                for (int j = 0; j < 4; j++) {
                    float v = sc[nt][j] * scale;
                    int col = colb + (j & 1);
                    int row = (j < 2) ? row_lo : row_hi;
                    if (col > row) v = -INFINITY;
                    sc[nt][j] = v;
                    if (j < 2) tmax0 = fmaxf(tmax0, v); else tmax1 = fmaxf(tmax1, v);
                }
            }
            tmax0 = fmaxf(tmax0, __shfl_xor_sync(0xffffffffu, tmax0, 1));
            tmax0 = fmaxf(tmax0, __shfl_xor_sync(0xffffffffu, tmax0, 2));
            tmax1 = fmaxf(tmax1, __shfl_xor_sync(0xffffffffu, tmax1, 1));
            tmax1 = fmaxf(tmax1, __shfl_xor_sync(0xffffffffu, tmax1, 2));

            float mn0 = fmaxf(mlo, tmax0), mn1 = fmaxf(mhi, tmax1);
            float c0 = __expf(mlo - mn0),  c1 = __expf(mhi - mn1);
            float s0 = 0.f, s1 = 0.f;
#pragma unroll
            for (int nt = 0; nt < 8; nt++) {
                float p0 = __expf(sc[nt][0] - mn0);
                float p1 = __expf(sc[nt][1] - mn0);
                float p2 = __expf(sc[nt][2] - mn1);
                float p3 = __expf(sc[nt][3] - mn1);
                sc[nt][0] = p0; sc[nt][1] = p1; sc[nt][2] = p2; sc[nt][3] = p3;
                s0 += p0 + p1; s1 += p2 + p3;
            }
            s0 += __shfl_xor_sync(0xffffffffu, s0, 1);
            s0 += __shfl_xor_sync(0xffffffffu, s0, 2);
            s1 += __shfl_xor_sync(0xffffffffu, s1, 1);
            s1 += __shfl_xor_sync(0xffffffffu, s1, 2);
            llo = llo * c0 + s0;  lhi = lhi * c1 + s1;
            mlo = mn0;  mhi = mn1;
#pragma unroll
            for (int nt = 0; nt < 16; nt++) {
                out[nt][0] *= c0; out[nt][1] *= c0;
                out[nt][2] *= c1; out[nt][3] *= c1;
            }

            // ---- P @ V
#pragma unroll
            for (int b = 0; b < 4; b++) {
                uint32_t ph[4], pl[4];
                ph[0] = pack_bf2(sc[2*b][0],   sc[2*b][1]);
                ph[1] = pack_bf2(sc[2*b][2],   sc[2*b][3]);
                ph[2] = pack_bf2(sc[2*b+1][0], sc[2*b+1][1]);
                ph[3] = pack_bf2(sc[2*b+1][2], sc[2*b+1][3]);
                pl[0] = pack_bf2(bf_lo(sc[2*b][0]),   bf_lo(sc[2*b][1]));
                pl[1] = pack_bf2(bf_lo(sc[2*b][2]),   bf_lo(sc[2*b][3]));
                pl[2] = pack_bf2(bf_lo(sc[2*b+1][0]), bf_lo(sc[2*b+1][1]));
                pl[3] = pack_bf2(bf_lo(sc[2*b+1][2]), bf_lo(sc[2*b+1][3]));

                const uint32_t vrow = (uint32_t)((b * 16 + (lane & 15)) * AROW + (lane >> 4) * 16);
#pragma unroll
                for (int nbp = 0; nbp < 8; nbp++) {
                    uint32_t vbh[4], vbl[4];
                    uint32_t o = vrow + nbp * 32;
                    ldsm_x4_t(vbh, Vh + o);
                    ldsm_x4_t(vbl, Vl + o);
#pragma unroll
                    for (int half = 0; half < 2; half++) {
                        float* c = out[2 * nbp + half];
                        mma16816(c, ph, &vbh[half * 2]);
                        mma16816(c, ph, &vbl[half * 2]);
                        mma16816(c, pl, &vbh[half * 2]);
                    }
                }
            }
        }
        if (++st == NSTG) st = 0;
    }

    // ---- epilogue: normalize, write bf16 hi/lo
    const float i0 = 1.f / llo, i1 = 1.f / lhi;
#pragma unroll
    for (int nt = 0; nt < 16; nt++) {
        int col = nt * 8 + (lane & 3) * 2;
        {
            float a = out[nt][0] * i0, b = out[nt][1] * i0;
            size_t idx = ((size_t)row_lo * NH + h) * HD + col;
            __nv_bfloat162 hv = __float22bfloat162_rn(make_float2(a, b));
            *(__nv_bfloat162*)(oh + idx) = hv;
            *(__nv_bfloat162*)(ol + idx) = __float22bfloat162_rn(
                make_float2(a - __bfloat162float(__low2bfloat16(hv)),
                            b - __bfloat162float(__high2bfloat16(hv))));
        }
        {
            float a = out[nt][2] * i1, b = out[nt][3] * i1;
            size_t idx = ((size_t)row_hi * NH + h) * HD + col;
            __nv_bfloat162 hv = __float22bfloat162_rn(make_float2(a, b));
            *(__nv_bfloat162*)(oh + idx) = hv;
            *(__nv_bfloat162*)(ol + idx) = __float22bfloat162_rn(
                make_float2(a - __bfloat162float(__low2bfloat16(hv)),
                            b - __bfloat162float(__high2bfloat16(hv))));
        }
    }
}

// ---------------------------------------------------------------------------
extern "C" void kernel_launch(void* const* d_in, const int* in_sizes, int n_in,
                              void* d_out, int out_size) {
    const float* hs   = (const float*)d_in[0];
    const float* cosp = (const float*)d_in[1];
    const float* sinp = (const float*)d_in[2];
    const float* Wq   = (const float*)d_in[3];
    const float* Wk   = (const float*)d_in[4];
    const float* Wv   = (const float*)d_in[5];
    const float* Wo   = (const float*)d_in[6];
    const float* qw   = (const float*)d_in[7];
    const float* kw   = (const float*)d_in[8];
    float* out = (float*)d_out;

    float* pqkv;
    cudaGetSymbolAddress((void**)&pqkv, g_qkv);

    __nv_bfloat16 *hsh,*hsl,*wh,*wl,*woh,*wol;
    __nv_bfloat16 *qh,*ql,*kh,*kl,*vh,*vl,*ohp,*olp;
    cudaGetSymbolAddress((void**)&hsh, g_hs_h); cudaGetSymbolAddress((void**)&hsl, g_hs_l);
    cudaGetSymbolAddress((void**)&wh,  g_w_h);  cudaGetSymbolAddress((void**)&wl,  g_w_l);
    cudaGetSymbolAddress((void**)&woh, g_wo_h); cudaGetSymbolAddress((void**)&wol, g_wo_l);
    cudaGetSymbolAddress((void**)&qh, g_qh); cudaGetSymbolAddress((void**)&ql, g_ql);
    cudaGetSymbolAddress((void**)&kh, g_kh); cudaGetSymbolAddress((void**)&kl, g_kl);
    cudaGetSymbolAddress((void**)&vh, g_vh); cudaGetSymbolAddress((void**)&vl, g_vl);
    cudaGetSymbolAddress((void**)&ohp, g_oh); cudaGetSymbolAddress((void**)&olp, g_ol);

    cudaFuncSetAttribute(gemm_tc, cudaFuncAttributeMaxDynamicSharedMemorySize, GEMM_DSM);
    cudaFuncSetAttribute(attention_tc, cudaFuncAttributeMaxDynamicSharedMemorySize, ADSM);

    // launch 0: hs split
    split_kernel<<<(S_LEN*HID + 255)/256, 256>>>(hs, hsh, hsl, S_LEN*HID);
    // launch 1: merged Wq|Wk|Wv split
    split_weights<<<(WQN + 2*WKN + 255)/256, 256>>>(Wq, Wk, Wv, wh, wl);
    // launch 2: Wo split (independent)
    split_kernel<<<(HID*NQD + 255)/256, 256>>>(Wo, woh, wol, HID*NQD);
    // launch 3 (ncu capture slot): fused QKV projection [2048, 6144]
    gemm_tc<<<dim3(NQKV/128, S_LEN/128), 256, GEMM_DSM>>>(hsh, hsl, wh, wl, pqkv, NQKV, HID);

    // rmsnorm+rope -> bf16 hi/lo (warp per head)
    rmsnorm_rope_split<<<dim3(S_LEN, NH/8),  256>>>(pqkv,       NQKV, qw, cosp, sinp, NH,  qh, ql);
    rmsnorm_rope_split<<<dim3(S_LEN, NKV/8), 256>>>(pqkv + NQD, NQKV, kw, cosp, sinp, NKV, kh, kl);
    split_strided<<<(S_LEN*NKD + 255)/256, 256>>>(pqkv + NQD + NKD, NQKV, NKD, vh, vl, S_LEN*NKD);

    // flash attention (HMMA), R5 2-D grid
    attention_tc<<<dim3(S_LEN/AQ, NH), 256, ADSM>>>(qh, ql, kh, kl, vh, vl, ohp, olp);

    // output projection
    gemm_tc<<<dim3(HID/128, S_LEN/128), 256, GEMM_DSM>>>(ohp, olp, woh, wol, out, HID, NQD);
}

// round 10
// speedup vs baseline: 1.7996x; 1.2336x over previous
#include <cuda_runtime.h>
#include <cuda_bf16.h>
#include <math.h>
#include <stdint.h>

#define S_LEN 2048
#define HID   2560
#define NH    32
#define NKV   8
#define HD    128
#define NQD   (NH*HD)     // 4096
#define NKD   (NKV*HD)    // 1024
#define NQKV  (NQD+2*NKD) // 6144

// fp32 scratch
__device__ float g_qkv[S_LEN * NQKV];   // q | k | v per row
__device__ float g_att[S_LEN * NQD];    // attention output (fp32, O-proj input)

// bf16 hi/lo scratch for attention operands
__device__ __nv_bfloat16 g_qh[S_LEN*NQD], g_ql[S_LEN*NQD];
__device__ __nv_bfloat16 g_kh[S_LEN*NKD], g_kl[S_LEN*NKD];
__device__ __nv_bfloat16 g_vh[S_LEN*NKD], g_vl[S_LEN*NKD];

// ---------------------------------------------------------------------------
__device__ __forceinline__ uint32_t s2u(const void* p) {
    uint32_t a;
    asm("{ .reg .u64 t; cvta.to.shared.u64 t, %1; cvt.u32.u64 %0, t; }" : "=r"(a) : "l"(p));
    return a;
}
__device__ __forceinline__ void ldsm_x4(uint32_t* r, uint32_t addr) {
    asm volatile("ldmatrix.sync.aligned.m8n8.x4.shared.b16 {%0,%1,%2,%3}, [%4];"
                 : "=r"(r[0]), "=r"(r[1]), "=r"(r[2]), "=r"(r[3]) : "r"(addr));
}
__device__ __forceinline__ void ldsm_x4_t(uint32_t* r, uint32_t addr) {
    asm volatile("ldmatrix.sync.aligned.m8n8.x4.trans.shared.b16 {%0,%1,%2,%3}, [%4];"
                 : "=r"(r[0]), "=r"(r[1]), "=r"(r[2]), "=r"(r[3]) : "r"(addr));
}
__device__ __forceinline__ void mma16816(float* c, const uint32_t* a, const uint32_t* b) {
    asm volatile("mma.sync.aligned.m16n8k16.row.col.f32.bf16.bf16.f32 "
                 "{%0,%1,%2,%3}, {%4,%5,%6,%7}, {%8,%9}, {%0,%1,%2,%3};"
                 : "+f"(c[0]), "+f"(c[1]), "+f"(c[2]), "+f"(c[3])
                 : "r"(a[0]), "r"(a[1]), "r"(a[2]), "r"(a[3]), "r"(b[0]), "r"(b[1]));
}
__device__ __forceinline__ void mma_tf32(float* c, const uint32_t* a, const uint32_t* b) {
    asm volatile("mma.sync.aligned.m16n8k8.row.col.f32.tf32.tf32.f32 "
                 "{%0,%1,%2,%3}, {%4,%5,%6,%7}, {%8,%9}, {%0,%1,%2,%3};"
                 : "+f"(c[0]), "+f"(c[1]), "+f"(c[2]), "+f"(c[3])
                 : "r"(a[0]), "r"(a[1]), "r"(a[2]), "r"(a[3]), "r"(b[0]), "r"(b[1]));
}
__device__ __forceinline__ void cvt4_tf32(uint32_t* r) {
#pragma unroll
    for (int i = 0; i < 4; i++)
        asm volatile("cvt.rna.tf32.f32 %0, %0;" : "+r"(r[i]));
}
__device__ __forceinline__ void cp16(uint32_t dst, const void* src) {
    asm volatile("cp.async.cg.shared.global [%0], [%1], 16;" :: "r"(dst), "l"(src));
}
__device__ __forceinline__ uint32_t pack_bf2(float x, float y) {
    __nv_bfloat162 t = __float22bfloat162_rn(make_float2(x, y));
    return *(uint32_t*)&t;
}
__device__ __forceinline__ float bf_lo(float x) {
    return x - __bfloat162float(__float2bfloat16(x));
}

// ---------------------------------------------------------------------------
// tf32 HMMA GEMM: C[M,N] = A[M,K] @ B[N,K]^T, fp32 in/out, fp32 acc.
// 128x128 CTA tile, BK=32, 8 warps (64x32 warp tile), 3-stage cp.async,
// 2 CTAs/SM. A/B staged as fp32 rows of 32 elems (128B + 16B pad).
// ---------------------------------------------------------------------------
#define AROWF  144                 // 32 fp32 + 16B pad
#define ATILEF (128*AROWF)         // 18432
#define STGF   (2*ATILEF)          // 36864 (A + B)
#define GSTG   3
#define GEMM_DSM (GSTG*STGF)       // 110592

__global__ __launch_bounds__(256, 2) void gemm_tf32(
    const float* __restrict__ A, const float* __restrict__ B,
    float* __restrict__ C, int N, int K)
{
    extern __shared__ __align__(128) char sm_raw[];
    const uint32_t sbase = s2u(sm_raw);

    const int tid  = threadIdx.x;
    const int wid  = tid >> 5;
    const int lane = tid & 31;
    const int m0 = blockIdx.y * 128, n0 = blockIdx.x * 128;
    const int m0w = (wid >> 2) * 64, n0w = (wid & 3) * 32;

    auto load_stage = [&](int c, int st) {
        const int k0 = c * 32;
#pragma unroll
        for (int j = 0; j < 8; j++) {
            int chunk = tid + j * 256;          // 2048 chunks of 16B
            int tile = chunk >> 10;             // 0=A, 1=B
            int idx  = chunk & 1023;
            int row = idx >> 3, seg = idx & 7;
            uint32_t dst = sbase + st * STGF + tile * ATILEF + row * AROWF + seg * 16;
            const float* src = tile ? (B + (size_t)(n0 + row) * K + k0 + seg * 4)
                                    : (A + (size_t)(m0 + row) * K + k0 + seg * 4);
            cp16(dst, src);
        }
        asm volatile("cp.async.commit_group;" ::: "memory");
    };

    float acc[4][4][4];
#pragma unroll
    for (int a = 0; a < 4; a++)
#pragma unroll
        for (int b = 0; b < 4; b++)
#pragma unroll
            for (int c = 0; c < 4; c++) acc[a][b][c] = 0.f;

    const int NC = K / 32;
    load_stage(0, 0);
    if (1 < NC) load_stage(1, 1);

    int st = 0;
    for (int c = 0; c < NC; c++) {
        const int rem = NC - 1 - c;
        if (rem >= 1) asm volatile("cp.async.wait_group 1;" ::: "memory");
        else          asm volatile("cp.async.wait_group 0;" ::: "memory");
        __syncthreads();
        if (c + 2 < NC) {
            int st2 = st + 2; if (st2 >= GSTG) st2 -= GSTG;
            load_stage(c + 2, st2);
        }

        const uint32_t aBase = sbase + st * STGF;
        const uint32_t bBase = aBase + ATILEF;
        const uint32_t aOff0 = (uint32_t)((m0w + (lane & 15)) * AROWF + ((lane >> 4) & 1) * 16);
        const uint32_t bOff0 = (uint32_t)((n0w + (lane & 15)) * AROWF + ((lane >> 4) & 1) * 16);

#pragma unroll
        for (int ks = 0; ks < 4; ks++) {
            const uint32_t kb = ks * 32;
            uint32_t a[4][4];
#pragma unroll
            for (int mt = 0; mt < 4; mt++) {
                ldsm_x4(a[mt], aBase + aOff0 + mt * 16 * AROWF + kb);
                cvt4_tf32(a[mt]);
            }
            uint32_t bf[4][2];
#pragma unroll
            for (int nb = 0; nb < 2; nb++) {
                uint32_t bq[4];
                ldsm_x4(bq, bBase + bOff0 + nb * 16 * AROWF + kb);
                cvt4_tf32(bq);
                bf[2*nb][0]   = bq[0]; bf[2*nb][1]   = bq[2];
                bf[2*nb+1][0] = bq[1]; bf[2*nb+1][1] = bq[3];
            }
#pragma unroll
            for (int mt = 0; mt < 4; mt++)
#pragma unroll
                for (int nt = 0; nt < 4; nt++)
                    mma_tf32(acc[mt][nt], a[mt], bf[nt]);
        }
        if (++st == GSTG) st = 0;
    }

    const int row0 = m0 + m0w + (lane >> 2);
    const int col0 = n0 + n0w + (lane & 3) * 2;
#pragma unroll
    for (int mt = 0; mt < 4; mt++)
#pragma unroll
        for (int nt = 0; nt < 4; nt++) {
            float* p0 = C + (size_t)(row0 + mt * 16) * N + col0 + nt * 8;
            *(float2*)p0 = make_float2(acc[mt][nt][0], acc[mt][nt][1]);
            float* p1 = p0 + 8 * (size_t)N;
            *(float2*)p1 = make_float2(acc[mt][nt][2], acc[mt][nt][3]);
        }
}

// ---------------------------------------------------------------------------
// RMSNorm + RoPE body (warp-per-head) -> bf16 hi/lo
// ---------------------------------------------------------------------------
__device__ __forceinline__ void rms_rope_row(
    const float* __restrict__ row, const float* __restrict__ w,
    const float* __restrict__ cosp, const float* __restrict__ sinp,
    int s, int lane, __nv_bfloat16* __restrict__ oh, __nv_bfloat16* __restrict__ ol,
    size_t oidx)
{
    float4 x = *(const float4*)(row + lane * 4);
    float v = x.x * x.x + x.y * x.y + x.z * x.z + x.w * x.w;
#pragma unroll
    for (int o = 16; o > 0; o >>= 1) v += __shfl_xor_sync(0xffffffffu, v, o);
    float r = rsqrtf(v * (1.0f / HD) + 1e-6f);

    float4 wv = *(const float4*)(w + lane * 4);
    float4 nx = make_float4(x.x * r * wv.x, x.y * r * wv.y, x.z * r * wv.z, x.w * r * wv.w);

    float4 p;
    p.x = __shfl_xor_sync(0xffffffffu, nx.x, 16);
    p.y = __shfl_xor_sync(0xffffffffu, nx.y, 16);
    p.z = __shfl_xor_sync(0xffffffffu, nx.z, 16);
    p.w = __shfl_xor_sync(0xffffffffu, nx.w, 16);
    const float sgn = (lane < 16) ? -1.f : 1.f;

    float4 c = *(const float4*)(cosp + s * HD + lane * 4);
    float4 sn = *(const float4*)(sinp + s * HD + lane * 4);
    float y0 = nx.x * c.x + sgn * p.x * sn.x;
    float y1 = nx.y * c.y + sgn * p.y * sn.y;
    float y2 = nx.z * c.z + sgn * p.z * sn.z;
    float y3 = nx.w * c.w + sgn * p.w * sn.w;

    __nv_bfloat162 h0 = __float22bfloat162_rn(make_float2(y0, y1));
    __nv_bfloat162 h1 = __float22bfloat162_rn(make_float2(y2, y3));
    *(__nv_bfloat162*)(oh + oidx)     = h0;
    *(__nv_bfloat162*)(oh + oidx + 2) = h1;
    *(__nv_bfloat162*)(ol + oidx)     = __float22bfloat162_rn(
        make_float2(y0 - __bfloat162float(__low2bfloat16(h0)),
                    y1 - __bfloat162float(__high2bfloat16(h0))));
    *(__nv_bfloat162*)(ol + oidx + 2) = __float22bfloat162_rn(
        make_float2(y2 - __bfloat162float(__low2bfloat16(h1)),
                    y3 - __bfloat162float(__high2bfloat16(h1))));
}

// Q: grid (S_LEN, NH/8), 256 threads
__global__ __launch_bounds__(256) void post_q(
    const float* __restrict__ qkv, const float* __restrict__ qw,
    const float* __restrict__ cosp, const float* __restrict__ sinp,
    __nv_bfloat16* __restrict__ qh, __nv_bfloat16* __restrict__ ql)
{
    const int warp = threadIdx.x >> 5, lane = threadIdx.x & 31;
    const int s = blockIdx.x;
    const int h = blockIdx.y * 8 + warp;
    rms_rope_row(qkv + (size_t)s * NQKV + h * HD, qw, cosp, sinp, s, lane,
                 qh, ql, ((size_t)s * NH + h) * HD + lane * 4);
}

// K rms+rope (y=0) and V split (y=1): grid (S_LEN, 2), 256 threads
__global__ __launch_bounds__(256) void post_kv(
    const float* __restrict__ qkv, const float* __restrict__ kw,
    const float* __restrict__ cosp, const float* __restrict__ sinp,
    __nv_bfloat16* __restrict__ kh, __nv_bfloat16* __restrict__ kl,
    __nv_bfloat16* __restrict__ vh, __nv_bfloat16* __restrict__ vl)
{
    const int warp = threadIdx.x >> 5, lane = threadIdx.x & 31;
    const int s = blockIdx.x;
    if (blockIdx.y == 0) {
        const int h = warp;      // 8 kv heads
        rms_rope_row(qkv + (size_t)s * NQKV + NQD + h * HD, kw, cosp, sinp, s, lane,
                     kh, kl, ((size_t)s * NKV + h) * HD + lane * 4);
    } else {
        const int i = threadIdx.x * 4;   // 1024 elems per row
        float4 x = *(const float4*)(qkv + (size_t)s * NQKV + NQD + NKD + i);
        const size_t idx = (size_t)s * NKD + i;
        __nv_bfloat162 h0 = __float22bfloat162_rn(make_float2(x.x, x.y));
        __nv_bfloat162 h1 = __float22bfloat162_rn(make_float2(x.z, x.w));
        *(__nv_bfloat162*)(vh + idx)     = h0;
        *(__nv_bfloat162*)(vh + idx + 2) = h1;
        *(__nv_bfloat162*)(vl + idx)     = __float22bfloat162_rn(
            make_float2(x.x - __bfloat162float(__low2bfloat16(h0)),
                        x.y - __bfloat162float(__high2bfloat16(h0))));
        *(__nv_bfloat162*)(vl + idx + 2) = __float22bfloat162_rn(
            make_float2(x.z - __bfloat162float(__low2bfloat16(h1)),
                        x.w - __bfloat162float(__high2bfloat16(h1))));
    }
}

// ---------------------------------------------------------------------------
// HMMA flash attention, bf16 hi/lo, 3-stage cp.async, fp32 output.
// CTA: 128 queries x 1 head, 8 warps. KV tiles of 64. 2-D grid.
// ---------------------------------------------------------------------------
#define AQ    128
#define AK    64
#define AROW  272
#define ATILE (64*AROW)           // 17408
#define ASTG  (4*ATILE)           // 69632
#define QTILE (128*AROW)          // 34816
#define NSTG  3
#define ADSM  (NSTG*ASTG)         // 208896

__global__ __launch_bounds__(256, 1) void attention_tc(
    const __nv_bfloat16* __restrict__ qh, const __nv_bfloat16* __restrict__ ql,
    const __nv_bfloat16* __restrict__ kh, const __nv_bfloat16* __restrict__ kl,
    const __nv_bfloat16* __restrict__ vh, const __nv_bfloat16* __restrict__ vl,
    float* __restrict__ o)
{
    extern __shared__ __align__(128) char sm_raw[];
    const uint32_t sbase = s2u(sm_raw);
    const int tid = threadIdx.x, wid = tid >> 5, lane = tid & 31;
    const int m0 = blockIdx.x * AQ;
    const int h = blockIdx.y, hk = h >> 2;
    const float scale = 0.08838834764831845f;

#pragma unroll
    for (int i = 0; i < 16; i++) {
        int c = tid + i * 256;
        int t = c >> 11;
        int row = (c >> 4) & 127, pos = c & 15;
        const __nv_bfloat16* src = t ? ql : qh;
        cp16(sbase + t * QTILE + row * AROW + pos * 16,
             src + ((size_t)(m0 + row) * NH + h) * HD + pos * 8);
    }
    asm volatile("cp.async.commit_group;" ::: "memory");
    asm volatile("cp.async.wait_group 0;" ::: "memory");
    __syncthreads();

    uint32_t qfh[8][4], qfl[8][4];
    {
        const uint32_t aOff = (uint32_t)((wid * 16 + (lane & 15)) * AROW + ((lane >> 4) & 1) * 16);
#pragma unroll
        for (int ks = 0; ks < 8; ks++) {
            ldsm_x4(qfh[ks], sbase + aOff + ks * 32);
            ldsm_x4(qfl[ks], sbase + QTILE + aOff + ks * 32);
        }
    }
    __syncthreads();

    auto load_kv = [&](int t, int st) {
        const int n0 = t * AK;
#pragma unroll
        for (int i = 0; i < 16; i++) {
            int c = tid + i * 256;
            int tl = c >> 10;
            int row = (c >> 4) & 63, pos = c & 15;
            const __nv_bfloat16* src = (tl == 0) ? kh : (tl == 1) ? kl : (tl == 2) ? vh : vl;
            cp16(sbase + st * ASTG + tl * ATILE + row * AROW + pos * 16,
                 src + ((size_t)(n0 + row) * NKV + hk) * HD + pos * 8);
        }
        asm volatile("cp.async.commit_group;" ::: "memory");
    };

    float out[16][4];
#pragma unroll
    for (int i = 0; i < 16; i++)
#pragma unroll
        for (int j = 0; j < 4; j++) out[i][j] = 0.f;
    float mlo = -INFINITY, mhi = -INFINITY, llo = 0.f, lhi = 0.f;

    const int row_lo = m0 + wid * 16 + (lane >> 2);
    const int row_hi = row_lo + 8;
    const int wlast  = m0 + wid * 16 + 15;

    const int NT = m0 / AK + 2;
    load_kv(0, 0);
    if (1 < NT) load_kv(1, 1);

    int st = 0;
    for (int t = 0; t < NT; t++) {
        const int n0 = t * AK;
        const int rem = NT - 1 - t;
        if (rem >= 1) asm volatile("cp.async.wait_group 1;" ::: "memory");
        else          asm volatile("cp.async.wait_group 0;" ::: "memory");
        __syncthreads();
        if (t + 2 < NT) {
            int st2 = st + 2; if (st2 >= NSTG) st2 -= NSTG;
            load_kv(t + 2, st2);
        }

        if (n0 <= wlast) {
            const uint32_t Kh = sbase + st * ASTG;
            const uint32_t Kl = Kh + ATILE;
            const uint32_t Vh = Kh + 2 * ATILE;
            const uint32_t Vl = Kh + 3 * ATILE;

            float sc[8][4];
#pragma unroll
            for (int i = 0; i < 8; i++)
#pragma unroll
                for (int j = 0; j < 4; j++) sc[i][j] = 0.f;

            const uint32_t bOff = (uint32_t)((((lane >> 1) & 8) + (lane & 7)) * AROW + (lane & 8) * 2);
#pragma unroll
            for (int ks = 0; ks < 8; ks++) {
#pragma unroll
                for (int nt2 = 0; nt2 < 4; nt2++) {
                    uint32_t kbh[4], kbl[4];
                    uint32_t off = bOff + nt2 * 16 * AROW + ks * 32;
                    ldsm_x4(kbh, Kh + off);
                    ldsm_x4(kbl, Kl + off);
#pragma unroll
                    for (int half = 0; half < 2; half++) {
                        float* c = sc[2 * nt2 + half];
                        mma16816(c, qfh[ks], &kbh[half * 2]);
                        mma16816(c, qfh[ks], &kbl[half * 2]);
                        mma16816(c, qfl[ks], &kbh[half * 2]);
                    }
                }
            }

            float tmax0 = -INFINITY, tmax1 = -INFINITY;
#pragma unroll
            for (int nt = 0; nt < 8; nt++) {
                int colb = n0 + nt * 8 + (lane & 3) * 2;
#pragma unroll
                for (int j = 0; j < 4; j++) {
                    float v = sc[nt][j] * scale;
                    int col = colb + (j & 1);
                    int row = (j < 2) ? row_lo : row_hi;
                    if (col > row) v = -INFINITY;
                    sc[nt][j] = v;
                    if (j < 2) tmax0 = fmaxf(tmax0, v); else tmax1 = fmaxf(tmax1, v);
                }
            }
            tmax0 = fmaxf(tmax0, __shfl_xor_sync(0xffffffffu, tmax0, 1));
            tmax0 = fmaxf(tmax0, __shfl_xor_sync(0xffffffffu, tmax0, 2));
            tmax1 = fmaxf(tmax1, __shfl_xor_sync(0xffffffffu, tmax1, 1));
            tmax1 = fmaxf(tmax1, __shfl_xor_sync(0xffffffffu, tmax1, 2));

            float mn0 = fmaxf(mlo, tmax0), mn1 = fmaxf(mhi, tmax1);
            float c0 = __expf(mlo - mn0),  c1 = __expf(mhi - mn1);
            float s0 = 0.f, s1 = 0.f;
#pragma unroll
            for (int nt = 0; nt < 8; nt++) {
                float p0 = __expf(sc[nt][0] - mn0);
                float p1 = __expf(sc[nt][1] - mn0);
                float p2 = __expf(sc[nt][2] - mn1);
                float p3 = __expf(sc[nt][3] - mn1);
                sc[nt][0] = p0; sc[nt][1] = p1; sc[nt][2] = p2; sc[nt][3] = p3;
                s0 += p0 + p1; s1 += p2 + p3;
            }
            s0 += __shfl_xor_sync(0xffffffffu, s0, 1);
            s0 += __shfl_xor_sync(0xffffffffu, s0, 2);
            s1 += __shfl_xor_sync(0xffffffffu, s1, 1);
            s1 += __shfl_xor_sync(0xffffffffu, s1, 2);
            llo = llo * c0 + s0;  lhi = lhi * c1 + s1;
            mlo = mn0;  mhi = mn1;
#pragma unroll
            for (int nt = 0; nt < 16; nt++) {
                out[nt][0] *= c0; out[nt][1] *= c0;
                out[nt][2] *= c1; out[nt][3] *= c1;
            }

#pragma unroll
            for (int b = 0; b < 4; b++) {
                uint32_t ph[4], pl[4];
                ph[0] = pack_bf2(sc[2*b][0],   sc[2*b][1]);
                ph[1] = pack_bf2(sc[2*b][2],   sc[2*b][3]);
                ph[2] = pack_bf2(sc[2*b+1][0], sc[2*b+1][1]);
                ph[3] = pack_bf2(sc[2*b+1][2], sc[2*b+1][3]);
                pl[0] = pack_bf2(bf_lo(sc[2*b][0]),   bf_lo(sc[2*b][1]));
                pl[1] = pack_bf2(bf_lo(sc[2*b][2]),   bf_lo(sc[2*b][3]));
                pl[2] = pack_bf2(bf_lo(sc[2*b+1][0]), bf_lo(sc[2*b+1][1]));
                pl[3] = pack_bf2(bf_lo(sc[2*b+1][2]), bf_lo(sc[2*b+1][3]));

                const uint32_t vrow = (uint32_t)((b * 16 + (lane & 15)) * AROW + (lane >> 4) * 16);
#pragma unroll
                for (int nbp = 0; nbp < 8; nbp++) {
                    uint32_t vbh[4], vbl[4];
                    uint32_t off = vrow + nbp * 32;
                    ldsm_x4_t(vbh, Vh + off);
                    ldsm_x4_t(vbl, Vl + off);
#pragma unroll
                    for (int half = 0; half < 2; half++) {
                        float* c = out[2 * nbp + half];
                        mma16816(c, ph, &vbh[half * 2]);
                        mma16816(c, ph, &vbl[half * 2]);
                        mma16816(c, pl, &vbh[half * 2]);
                    }
                }
            }
        }
        if (++st == NSTG) st = 0;
    }

    // ---- epilogue: normalize, write fp32
    const float i0 = 1.f / llo, i1 = 1.f / lhi;
#pragma unroll
    for (int nt = 0; nt < 16; nt++) {
        int col = nt * 8 + (lane & 3) * 2;
        *(float2*)(o + ((size_t)row_lo * NH + h) * HD + col) =
            make_float2(out[nt][0] * i0, out[nt][1] * i0);
        *(float2*)(o + ((size_t)row_hi * NH + h) * HD + col) =
            make_float2(out[nt][2] * i1, out[nt][3] * i1);
    }
}

// ---------------------------------------------------------------------------
extern "C" void kernel_launch(void* const* d_in, const int* in_sizes, int n_in,
                              void* d_out, int out_size) {
    const float* hs   = (const float*)d_in[0];
    const float* cosp = (const float*)d_in[1];
    const float* sinp = (const float*)d_in[2];
    const float* Wq   = (const float*)d_in[3];
    const float* Wk   = (const float*)d_in[4];
    const float* Wv   = (const float*)d_in[5];
    const float* Wo   = (const float*)d_in[6];
    const float* qw   = (const float*)d_in[7];
    const float* kw   = (const float*)d_in[8];
    float* out = (float*)d_out;
    (void)Wk; (void)Wv;   // accessed via contiguity? NO — separate tensors; see below.

    float *pqkv, *patt;
    cudaGetSymbolAddress((void**)&pqkv, g_qkv);
    cudaGetSymbolAddress((void**)&patt, g_att);

    __nv_bfloat16 *qh,*ql,*kh,*kl,*vh,*vl;
    cudaGetSymbolAddress((void**)&qh, g_qh); cudaGetSymbolAddress((void**)&ql, g_ql);
    cudaGetSymbolAddress((void**)&kh, g_kh); cudaGetSymbolAddress((void**)&kl, g_kl);
    cudaGetSymbolAddress((void**)&vh, g_vh); cudaGetSymbolAddress((void**)&vl, g_vl);

    cudaFuncSetAttribute(gemm_tf32, cudaFuncAttributeMaxDynamicSharedMemorySize, GEMM_DSM);
    cudaFuncSetAttribute(attention_tc, cudaFuncAttributeMaxDynamicSharedMemorySize, ADSM);

    // launch 0-2: Q/K/V projections (tf32, fp32 inputs direct; separate weight tensors)
    gemm_tf32<<<dim3(NQD/128, S_LEN/128), 256, GEMM_DSM>>>(hs, Wq, pqkv,                 NQKV, HID);
    // K and V write into the same combined row buffer at column offsets via pointer math:
    // C pointer offset by columns works because row stride N is passed as NQKV.
    gemm_tf32<<<dim3(NKD/128, S_LEN/128), 256, GEMM_DSM>>>(hs, Wk, pqkv + NQD,           NQKV, HID);
    gemm_tf32<<<dim3(NKD/128, S_LEN/128), 256, GEMM_DSM>>>(hs, Wv, pqkv + NQD + NKD,     NQKV, HID);

    // launch 3... shifted; put post kernels then attention
    post_q <<<dim3(S_LEN, NH/8), 256>>>(pqkv, qw, cosp, sinp, qh, ql);
    post_kv<<<dim3(S_LEN, 2),    256>>>(pqkv, kw, cosp, sinp, kh, kl, vh, vl);

    // flash attention (HMMA bf16-split)
    attention_tc<<<dim3(S_LEN/AQ, NH), 256, ADSM>>>(qh, ql, kh, kl, vh, vl, patt);

    // output projection (tf32, fp32 direct)
    gemm_tf32<<<dim3(HID/128, S_LEN/128), 256, GEMM_DSM>>>(patt, Wo, out, HID, NQD);
}

// round 11
// speedup vs baseline: 1.8253x; 1.0143x over previous
#include <cuda_runtime.h>
#include <cuda_bf16.h>
#include <math.h>
#include <stdint.h>

#define S_LEN 2048
#define HID   2560
#define NH    32
#define NKV   8
#define HD    128
#define NQD   (NH*HD)     // 4096
#define NKD   (NKV*HD)    // 1024
#define NQKV  (NQD+2*NKD) // 6144

// fp32 scratch
__device__ float g_qkv[S_LEN * NQKV];   // q | k | v per row
__device__ float g_att[S_LEN * NQD];    // attention output (fp32, O-proj input)

// bf16 hi/lo scratch for attention operands
__device__ __nv_bfloat16 g_qh[S_LEN*NQD], g_ql[S_LEN*NQD];
__device__ __nv_bfloat16 g_kh[S_LEN*NKD], g_kl[S_LEN*NKD];
__device__ __nv_bfloat16 g_vh[S_LEN*NKD], g_vl[S_LEN*NKD];

// ---------------------------------------------------------------------------
__device__ __forceinline__ uint32_t s2u(const void* p) {
    uint32_t a;
    asm("{ .reg .u64 t; cvta.to.shared.u64 t, %1; cvt.u32.u64 %0, t; }" : "=r"(a) : "l"(p));
    return a;
}
__device__ __forceinline__ void ldsm_x4(uint32_t* r, uint32_t addr) {
    asm volatile("ldmatrix.sync.aligned.m8n8.x4.shared.b16 {%0,%1,%2,%3}, [%4];"
                 : "=r"(r[0]), "=r"(r[1]), "=r"(r[2]), "=r"(r[3]) : "r"(addr));
}
__device__ __forceinline__ void ldsm_x4_t(uint32_t* r, uint32_t addr) {
    asm volatile("ldmatrix.sync.aligned.m8n8.x4.trans.shared.b16 {%0,%1,%2,%3}, [%4];"
                 : "=r"(r[0]), "=r"(r[1]), "=r"(r[2]), "=r"(r[3]) : "r"(addr));
}
__device__ __forceinline__ void mma16816(float* c, const uint32_t* a, const uint32_t* b) {
    asm volatile("mma.sync.aligned.m16n8k16.row.col.f32.bf16.bf16.f32 "
                 "{%0,%1,%2,%3}, {%4,%5,%6,%7}, {%8,%9}, {%0,%1,%2,%3};"
                 : "+f"(c[0]), "+f"(c[1]), "+f"(c[2]), "+f"(c[3])
                 : "r"(a[0]), "r"(a[1]), "r"(a[2]), "r"(a[3]), "r"(b[0]), "r"(b[1]));
}
__device__ __forceinline__ void mma_tf32(float* c, const uint32_t* a, const uint32_t* b) {
    asm volatile("mma.sync.aligned.m16n8k8.row.col.f32.tf32.tf32.f32 "
                 "{%0,%1,%2,%3}, {%4,%5,%6,%7}, {%8,%9}, {%0,%1,%2,%3};"
                 : "+f"(c[0]), "+f"(c[1]), "+f"(c[2]), "+f"(c[3])
                 : "r"(a[0]), "r"(a[1]), "r"(a[2]), "r"(a[3]), "r"(b[0]), "r"(b[1]));
}
__device__ __forceinline__ void cvt4_tf32(uint32_t* r) {
#pragma unroll
    for (int i = 0; i < 4; i++)
        asm volatile("cvt.rna.tf32.f32 %0, %0;" : "+r"(r[i]));
}
__device__ __forceinline__ void cp16(uint32_t dst, const void* src) {
    asm volatile("cp.async.cg.shared.global [%0], [%1], 16;" :: "r"(dst), "l"(src));
}
__device__ __forceinline__ uint32_t pack_bf2(float x, float y) {
    __nv_bfloat162 t = __float22bfloat162_rn(make_float2(x, y));
    return *(uint32_t*)&t;
}
__device__ __forceinline__ float bf_lo(float x) {
    return x - __bfloat162float(__float2bfloat16(x));
}

// ---------------------------------------------------------------------------
// tf32 HMMA GEMM: C[M,N] = A[M,K] @ B[N,K]^T, fp32 in/out, fp32 acc.
// 128x128 CTA tile, BK=32, 8 warps, 3-stage cp.async, 2 CTAs/SM.
// B selected per-CTA from {B0,B1,B2} by column tile (boundaries nb1/nb2,
// multiples of 128 so one CTA never straddles).
// ---------------------------------------------------------------------------
#define AROWF  144                 // 32 fp32 + 16B pad
#define ATILEF (128*AROWF)         // 18432
#define STGF   (2*ATILEF)          // 36864 (A + B)
#define GSTG   3
#define GEMM_DSM (GSTG*STGF)       // 110592

__global__ __launch_bounds__(256, 2) void gemm_tf32(
    const float* __restrict__ A,
    const float* __restrict__ B0, const float* __restrict__ B1,
    const float* __restrict__ B2, int nb1, int nb2,
    float* __restrict__ C, int N, int K)
{
    extern __shared__ __align__(128) char sm_raw[];
    const uint32_t sbase = s2u(sm_raw);

    const int tid  = threadIdx.x;
    const int wid  = tid >> 5;
    const int lane = tid & 31;
    const int m0 = blockIdx.y * 128, n0 = blockIdx.x * 128;
    const int m0w = (wid >> 2) * 64, n0w = (wid & 3) * 32;

    // per-CTA weight-tensor select (tile boundaries are multiples of 128)
    const float* Bsel;
    int nbase;
    if (n0 < nb1)      { Bsel = B0; nbase = n0; }
    else if (n0 < nb2) { Bsel = B1; nbase = n0 - nb1; }
    else               { Bsel = B2; nbase = n0 - nb2; }

    auto load_stage = [&](int c, int st) {
        const int k0 = c * 32;
#pragma unroll
        for (int j = 0; j < 8; j++) {
            int chunk = tid + j * 256;          // 2048 chunks of 16B
            int tile = chunk >> 10;             // 0=A, 1=B
            int idx  = chunk & 1023;
            int row = idx >> 3, seg = idx & 7;
            uint32_t dst = sbase + st * STGF + tile * ATILEF + row * AROWF + seg * 16;
            const float* src = tile ? (Bsel + (size_t)(nbase + row) * K + k0 + seg * 4)
                                    : (A + (size_t)(m0 + row) * K + k0 + seg * 4);
            cp16(dst, src);
        }
        asm volatile("cp.async.commit_group;" ::: "memory");
    };

    float acc[4][4][4];
#pragma unroll
    for (int a = 0; a < 4; a++)
#pragma unroll
        for (int b = 0; b < 4; b++)
#pragma unroll
            for (int c = 0; c < 4; c++) acc[a][b][c] = 0.f;

    const int NC = K / 32;
    load_stage(0, 0);
    if (1 < NC) load_stage(1, 1);

    int st = 0;
    for (int c = 0; c < NC; c++) {
        const int rem = NC - 1 - c;
        if (rem >= 1) asm volatile("cp.async.wait_group 1;" ::: "memory");
        else          asm volatile("cp.async.wait_group 0;" ::: "memory");
        __syncthreads();
        if (c + 2 < NC) {
            int st2 = st + 2; if (st2 >= GSTG) st2 -= GSTG;
            load_stage(c + 2, st2);
        }

        const uint32_t aBase = sbase + st * STGF;
        const uint32_t bBase = aBase + ATILEF;
        const uint32_t aOff0 = (uint32_t)((m0w + (lane & 15)) * AROWF + ((lane >> 4) & 1) * 16);
        const uint32_t bOff0 = (uint32_t)((n0w + (lane & 15)) * AROWF + ((lane >> 4) & 1) * 16);

#pragma unroll
        for (int ks = 0; ks < 4; ks++) {
            const uint32_t kb = ks * 32;
            uint32_t a[4][4];
#pragma unroll
            for (int mt = 0; mt < 4; mt++) {
                ldsm_x4(a[mt], aBase + aOff0 + mt * 16 * AROWF + kb);
                cvt4_tf32(a[mt]);
            }
            uint32_t bf[4][2];
#pragma unroll
            for (int nb = 0; nb < 2; nb++) {
                uint32_t bq[4];
                ldsm_x4(bq, bBase + bOff0 + nb * 16 * AROWF + kb);
                cvt4_tf32(bq);
                bf[2*nb][0]   = bq[0]; bf[2*nb][1]   = bq[2];
                bf[2*nb+1][0] = bq[1]; bf[2*nb+1][1] = bq[3];
            }
#pragma unroll
            for (int mt = 0; mt < 4; mt++)
#pragma unroll
                for (int nt = 0; nt < 4; nt++)
                    mma_tf32(acc[mt][nt], a[mt], bf[nt]);
        }
        if (++st == GSTG) st = 0;
    }

    const int row0 = m0 + m0w + (lane >> 2);
    const int col0 = n0 + n0w + (lane & 3) * 2;
#pragma unroll
    for (int mt = 0; mt < 4; mt++)
#pragma unroll
        for (int nt = 0; nt < 4; nt++) {
            float* p0 = C + (size_t)(row0 + mt * 16) * N + col0 + nt * 8;
            *(float2*)p0 = make_float2(acc[mt][nt][0], acc[mt][nt][1]);
            float* p1 = p0 + 8 * (size_t)N;
            *(float2*)p1 = make_float2(acc[mt][nt][2], acc[mt][nt][3]);
        }
}

// ---------------------------------------------------------------------------
// RMSNorm + RoPE body (warp-per-head) -> bf16 hi/lo
// ---------------------------------------------------------------------------
__device__ __forceinline__ void rms_rope_row(
    const float* __restrict__ row, const float* __restrict__ w,
    const float* __restrict__ cosp, const float* __restrict__ sinp,
    int s, int lane, __nv_bfloat16* __restrict__ oh, __nv_bfloat16* __restrict__ ol,
    size_t oidx)
{
    float4 x = *(const float4*)(row + lane * 4);
    float v = x.x * x.x + x.y * x.y + x.z * x.z + x.w * x.w;
#pragma unroll
    for (int o = 16; o > 0; o >>= 1) v += __shfl_xor_sync(0xffffffffu, v, o);
    float r = rsqrtf(v * (1.0f / HD) + 1e-6f);

    float4 wv = *(const float4*)(w + lane * 4);
    float4 nx = make_float4(x.x * r * wv.x, x.y * r * wv.y, x.z * r * wv.z, x.w * r * wv.w);

    float4 p;
    p.x = __shfl_xor_sync(0xffffffffu, nx.x, 16);
    p.y = __shfl_xor_sync(0xffffffffu, nx.y, 16);
    p.z = __shfl_xor_sync(0xffffffffu, nx.z, 16);
    p.w = __shfl_xor_sync(0xffffffffu, nx.w, 16);
    const float sgn = (lane < 16) ? -1.f : 1.f;

    float4 c = *(const float4*)(cosp + s * HD + lane * 4);
    float4 sn = *(const float4*)(sinp + s * HD + lane * 4);
    float y0 = nx.x * c.x + sgn * p.x * sn.x;
    float y1 = nx.y * c.y + sgn * p.y * sn.y;
    float y2 = nx.z * c.z + sgn * p.z * sn.z;
    float y3 = nx.w * c.w + sgn * p.w * sn.w;

    __nv_bfloat162 h0 = __float22bfloat162_rn(make_float2(y0, y1));
    __nv_bfloat162 h1 = __float22bfloat162_rn(make_float2(y2, y3));
    *(__nv_bfloat162*)(oh + oidx)     = h0;
    *(__nv_bfloat162*)(oh + oidx + 2) = h1;
    *(__nv_bfloat162*)(ol + oidx)     = __float22bfloat162_rn(
        make_float2(y0 - __bfloat162float(__low2bfloat16(h0)),
                    y1 - __bfloat162float(__high2bfloat16(h0))));
    *(__nv_bfloat162*)(ol + oidx + 2) = __float22bfloat162_rn(
        make_float2(y2 - __bfloat162float(__low2bfloat16(h1)),
                    y3 - __bfloat162float(__high2bfloat16(h1))));
}

// Q: grid (S_LEN, NH/8), 256 threads
__global__ __launch_bounds__(256) void post_q(
    const float* __restrict__ qkv, const float* __restrict__ qw,
    const float* __restrict__ cosp, const float* __restrict__ sinp,
    __nv_bfloat16* __restrict__ qh, __nv_bfloat16* __restrict__ ql)
{
    const int warp = threadIdx.x >> 5, lane = threadIdx.x & 31;
    const int s = blockIdx.x;
    const int h = blockIdx.y * 8 + warp;
    rms_rope_row(qkv + (size_t)s * NQKV + h * HD, qw, cosp, sinp, s, lane,
                 qh, ql, ((size_t)s * NH + h) * HD + lane * 4);
}

// K rms+rope (y=0) and V split (y=1): grid (S_LEN, 2), 256 threads
__global__ __launch_bounds__(256) void post_kv(
    const float* __restrict__ qkv, const float* __restrict__ kw,
    const float* __restrict__ cosp, const float* __restrict__ sinp,
    __nv_bfloat16* __restrict__ kh, __nv_bfloat16* __restrict__ kl,
    __nv_bfloat16* __restrict__ vh, __nv_bfloat16* __restrict__ vl)
{
    const int warp = threadIdx.x >> 5, lane = threadIdx.x & 31;
    const int s = blockIdx.x;
    if (blockIdx.y == 0) {
        const int h = warp;      // 8 kv heads
        rms_rope_row(qkv + (size_t)s * NQKV + NQD + h * HD, kw, cosp, sinp, s, lane,
                     kh, kl, ((size_t)s * NKV + h) * HD + lane * 4);
    } else {
        const int i = threadIdx.x * 4;   // 1024 elems per row
        float4 x = *(const float4*)(qkv + (size_t)s * NQKV + NQD + NKD + i);
        const size_t idx = (size_t)s * NKD + i;
        __nv_bfloat162 h0 = __float22bfloat162_rn(make_float2(x.x, x.y));
        __nv_bfloat162 h1 = __float22bfloat162_rn(make_float2(x.z, x.w));
        *(__nv_bfloat162*)(vh + idx)     = h0;
        *(__nv_bfloat162*)(vh + idx + 2) = h1;
        *(__nv_bfloat162*)(vl + idx)     = __float22bfloat162_rn(
            make_float2(x.x - __bfloat162float(__low2bfloat16(h0)),
                        x.y - __bfloat162float(__high2bfloat16(h0))));
        *(__nv_bfloat162*)(vl + idx + 2) = __float22bfloat162_rn(
            make_float2(x.z - __bfloat162float(__low2bfloat16(h1)),
                        x.w - __bfloat162float(__high2bfloat16(h1))));
    }
}

// ---------------------------------------------------------------------------
// HMMA flash attention, bf16 hi/lo, 3-stage cp.async, fp32 output.
// CTA: 128 queries x 1 head, 8 warps. KV tiles of 64. 2-D grid.
// ---------------------------------------------------------------------------
#define AQ    128
#define AK    64
#define AROW  272
#define ATILE (64*AROW)           // 17408
#define ASTG  (4*ATILE)           // 69632
#define QTILE (128*AROW)          // 34816
#define NSTG  3
#define ADSM  (NSTG*ASTG)         // 208896

__global__ __launch_bounds__(256, 1) void attention_tc(
    const __nv_bfloat16* __restrict__ qh, const __nv_bfloat16* __restrict__ ql,
    const __nv_bfloat16* __restrict__ kh, const __nv_bfloat16* __restrict__ kl,
    const __nv_bfloat16* __restrict__ vh, const __nv_bfloat16* __restrict__ vl,
    float* __restrict__ o)
{
    extern __shared__ __align__(128) char sm_raw[];
    const uint32_t sbase = s2u(sm_raw);
    const int tid = threadIdx.x, wid = tid >> 5, lane = tid & 31;
    const int m0 = blockIdx.x * AQ;
    const int h = blockIdx.y, hk = h >> 2;
    const float scale = 0.08838834764831845f;

#pragma unroll
    for (int i = 0; i < 16; i++) {
        int c = tid + i * 256;
        int t = c >> 11;
        int row = (c >> 4) & 127, pos = c & 15;
        const __nv_bfloat16* src = t ? ql : qh;
        cp16(sbase + t * QTILE + row * AROW + pos * 16,
             src + ((size_t)(m0 + row) * NH + h) * HD + pos * 8);
    }
    asm volatile("cp.async.commit_group;" ::: "memory");
    asm volatile("cp.async.wait_group 0;" ::: "memory");
    __syncthreads();

    uint32_t qfh[8][4], qfl[8][4];
    {
        const uint32_t aOff = (uint32_t)((wid * 16 + (lane & 15)) * AROW + ((lane >> 4) & 1) * 16);
#pragma unroll
        for (int ks = 0; ks < 8; ks++) {
            ldsm_x4(qfh[ks], sbase + aOff + ks * 32);
            ldsm_x4(qfl[ks], sbase + QTILE + aOff + ks * 32);
        }
    }
    __syncthreads();

    auto load_kv = [&](int t, int st) {
        const int n0 = t * AK;
#pragma unroll
        for (int i = 0; i < 16; i++) {
            int c = tid + i * 256;
            int tl = c >> 10;
            int row = (c >> 4) & 63, pos = c & 15;
            const __nv_bfloat16* src = (tl == 0) ? kh : (tl == 1) ? kl : (tl == 2) ? vh : vl;
            cp16(sbase + st * ASTG + tl * ATILE + row * AROW + pos * 16,
                 src + ((size_t)(n0 + row) * NKV + hk) * HD + pos * 8);
        }
        asm volatile("cp.async.commit_group;" ::: "memory");
    };

    float out[16][4];
#pragma unroll
    for (int i = 0; i < 16; i++)
#pragma unroll
        for (int j = 0; j < 4; j++) out[i][j] = 0.f;
    float mlo = -INFINITY, mhi = -INFINITY, llo = 0.f, lhi = 0.f;

    const int row_lo = m0 + wid * 16 + (lane >> 2);
    const int row_hi = row_lo + 8;
    const int wlast  = m0 + wid * 16 + 15;

    const int NT = m0 / AK + 2;
    load_kv(0, 0);
    if (1 < NT) load_kv(1, 1);

    int st = 0;
    for (int t = 0; t < NT; t++) {
        const int n0 = t * AK;
        const int rem = NT - 1 - t;
        if (rem >= 1) asm volatile("cp.async.wait_group 1;" ::: "memory");
        else          asm volatile("cp.async.wait_group 0;" ::: "memory");
        __syncthreads();
        if (t + 2 < NT) {
            int st2 = st + 2; if (st2 >= NSTG) st2 -= NSTG;
            load_kv(t + 2, st2);
        }

        if (n0 <= wlast) {
            const uint32_t Kh = sbase + st * ASTG;
            const uint32_t Kl = Kh + ATILE;
            const uint32_t Vh = Kh + 2 * ATILE;
            const uint32_t Vl = Kh + 3 * ATILE;

            float sc[8][4];
#pragma unroll
            for (int i = 0; i < 8; i++)
#pragma unroll
                for (int j = 0; j < 4; j++) sc[i][j] = 0.f;

            const uint32_t bOff = (uint32_t)((((lane >> 1) & 8) + (lane & 7)) * AROW + (lane & 8) * 2);
#pragma unroll
            for (int ks = 0; ks < 8; ks++) {
#pragma unroll
                for (int nt2 = 0; nt2 < 4; nt2++) {
                    uint32_t kbh[4], kbl[4];
                    uint32_t off = bOff + nt2 * 16 * AROW + ks * 32;
                    ldsm_x4(kbh, Kh + off);
                    ldsm_x4(kbl, Kl + off);
#pragma unroll
                    for (int half = 0; half < 2; half++) {
                        float* c = sc[2 * nt2 + half];
                        mma16816(c, qfh[ks], &kbh[half * 2]);
                        mma16816(c, qfh[ks], &kbl[half * 2]);
                        mma16816(c, qfl[ks], &kbh[half * 2]);
                    }
                }
            }

            float tmax0 = -INFINITY, tmax1 = -INFINITY;
#pragma unroll
            for (int nt = 0; nt < 8; nt++) {
                int colb = n0 + nt * 8 + (lane & 3) * 2;
#pragma unroll
                for (int j = 0; j < 4; j++) {
                    float v = sc[nt][j] * scale;
                    int col = colb + (j & 1);
                    int row = (j < 2) ? row_lo : row_hi;
                    if (col > row) v = -INFINITY;
                    sc[nt][j] = v;
                    if (j < 2) tmax0 = fmaxf(tmax0, v); else tmax1 = fmaxf(tmax1, v);
                }
            }
            tmax0 = fmaxf(tmax0, __shfl_xor_sync(0xffffffffu, tmax0, 1));
            tmax0 = fmaxf(tmax0, __shfl_xor_sync(0xffffffffu, tmax0, 2));
            tmax1 = fmaxf(tmax1, __shfl_xor_sync(0xffffffffu, tmax1, 1));
            tmax1 = fmaxf(tmax1, __shfl_xor_sync(0xffffffffu, tmax1, 2));

            float mn0 = fmaxf(mlo, tmax0), mn1 = fmaxf(mhi, tmax1);
            float c0 = __expf(mlo - mn0),  c1 = __expf(mhi - mn1);
            float s0 = 0.f, s1 = 0.f;
#pragma unroll
            for (int nt = 0; nt < 8; nt++) {
                float p0 = __expf(sc[nt][0] - mn0);
                float p1 = __expf(sc[nt][1] - mn0);
                float p2 = __expf(sc[nt][2] - mn1);
                float p3 = __expf(sc[nt][3] - mn1);
                sc[nt][0] = p0; sc[nt][1] = p1; sc[nt][2] = p2; sc[nt][3] = p3;
                s0 += p0 + p1; s1 += p2 + p3;
            }
            s0 += __shfl_xor_sync(0xffffffffu, s0, 1);
            s0 += __shfl_xor_sync(0xffffffffu, s0, 2);
            s1 += __shfl_xor_sync(0xffffffffu, s1, 1);
            s1 += __shfl_xor_sync(0xffffffffu, s1, 2);
            llo = llo * c0 + s0;  lhi = lhi * c1 + s1;
            mlo = mn0;  mhi = mn1;
#pragma unroll
            for (int nt = 0; nt < 16; nt++) {
                out[nt][0] *= c0; out[nt][1] *= c0;
                out[nt][2] *= c1; out[nt][3] *= c1;
            }

#pragma unroll
            for (int b = 0; b < 4; b++) {
                uint32_t ph[4], pl[4];
                ph[0] = pack_bf2(sc[2*b][0],   sc[2*b][1]);
                ph[1] = pack_bf2(sc[2*b][2],   sc[2*b][3]);
                ph[2] = pack_bf2(sc[2*b+1][0], sc[2*b+1][1]);
                ph[3] = pack_bf2(sc[2*b+1][2], sc[2*b+1][3]);
                pl[0] = pack_bf2(bf_lo(sc[2*b][0]),   bf_lo(sc[2*b][1]));
                pl[1] = pack_bf2(bf_lo(sc[2*b][2]),   bf_lo(sc[2*b][3]));
                pl[2] = pack_bf2(bf_lo(sc[2*b+1][0]), bf_lo(sc[2*b+1][1]));
                pl[3] = pack_bf2(bf_lo(sc[2*b+1][2]), bf_lo(sc[2*b+1][3]));

                const uint32_t vrow = (uint32_t)((b * 16 + (lane & 15)) * AROW + (lane >> 4) * 16);
#pragma unroll
                for (int nbp = 0; nbp < 8; nbp++) {
                    uint32_t vbh[4], vbl[4];
                    uint32_t off = vrow + nbp * 32;
                    ldsm_x4_t(vbh, Vh + off);
                    ldsm_x4_t(vbl, Vl + off);
#pragma unroll
                    for (int half = 0; half < 2; half++) {
                        float* c = out[2 * nbp + half];
                        mma16816(c, ph, &vbh[half * 2]);
                        mma16816(c, ph, &vbl[half * 2]);
                        mma16816(c, pl, &vbh[half * 2]);
                    }
                }
            }
        }
        if (++st == NSTG) st = 0;
    }

    // ---- epilogue: normalize, write fp32
    const float i0 = 1.f / llo, i1 = 1.f / lhi;
#pragma unroll
    for (int nt = 0; nt < 16; nt++) {
        int col = nt * 8 + (lane & 3) * 2;
        *(float2*)(o + ((size_t)row_lo * NH + h) * HD + col) =
            make_float2(out[nt][0] * i0, out[nt][1] * i0);
        *(float2*)(o + ((size_t)row_hi * NH + h) * HD + col) =
            make_float2(out[nt][2] * i1, out[nt][3] * i1);
    }
}

// ---------------------------------------------------------------------------
extern "C" void kernel_launch(void* const* d_in, const int* in_sizes, int n_in,
                              void* d_out, int out_size) {
    const float* hs   = (const float*)d_in[0];
    const float* cosp = (const float*)d_in[1];
    const float* sinp = (const float*)d_in[2];
    const float* Wq   = (const float*)d_in[3];
    const float* Wk   = (const float*)d_in[4];
    const float* Wv   = (const float*)d_in[5];
    const float* Wo   = (const float*)d_in[6];
    const float* qw   = (const float*)d_in[7];
    const float* kw   = (const float*)d_in[8];
    float* out = (float*)d_out;

    float *pqkv, *patt;
    cudaGetSymbolAddress((void**)&pqkv, g_qkv);
    cudaGetSymbolAddress((void**)&patt, g_att);

    __nv_bfloat16 *qh,*ql,*kh,*kl,*vh,*vl;
    cudaGetSymbolAddress((void**)&qh, g_qh); cudaGetSymbolAddress((void**)&ql, g_ql);
    cudaGetSymbolAddress((void**)&kh, g_kh); cudaGetSymbolAddress((void**)&kl, g_kl);
    cudaGetSymbolAddress((void**)&vh, g_vh); cudaGetSymbolAddress((void**)&vl, g_vl);

    cudaFuncSetAttribute(gemm_tf32, cudaFuncAttributeMaxDynamicSharedMemorySize, GEMM_DSM);
    cudaFuncSetAttribute(attention_tc, cudaFuncAttributeMaxDynamicSharedMemorySize, ADSM);

    // launch 0: fused QKV projection (one GEMM, per-CTA weight select)
    gemm_tf32<<<dim3(NQKV/128, S_LEN/128), 256, GEMM_DSM>>>(
        hs, Wq, Wk, Wv, NQD, NQD + NKD, pqkv, NQKV, HID);

    // launch 1-2: post-processing
    post_q <<<dim3(S_LEN, NH/8), 256>>>(pqkv, qw, cosp, sinp, qh, ql);
    post_kv<<<dim3(S_LEN, 2),    256>>>(pqkv, kw, cosp, sinp, kh, kl, vh, vl);

    // launch 3 (ncu capture slot): flash attention
    attention_tc<<<dim3(S_LEN/AQ, NH), 256, ADSM>>>(qh, ql, kh, kl, vh, vl, patt);

    // output projection
    gemm_tf32<<<dim3(HID/128, S_LEN/128), 256, GEMM_DSM>>>(
        patt, Wo, Wo, Wo, HID, HID, out, HID, NQD);
}